// round 10
// baseline (speedup 1.0000x reference)
#include <cuda_runtime.h>
#include <cuda_bf16.h>
#include <cstdint>

// LinearAttention via mma.sync bf16, cp.async double-buffered pipeline:
//   convert_x : X fp32 -> Xhi/Xlo bf16 [b][c][n]  (one-time split)
//   gemm_tc<0>: E = exp(W_k x); A staged once (fp32 split, full K), B = X bf16 via
//               cp.async double buffer; epilogue: exp -> Ehi/Elo bf16 + row sums
//   gemm_tc<1>: Spart = E X^T; A = E bf16, B = X bf16, both cp.async double-buffered
//   reduce_scale / ctx / u / m : tiny fp32 algebra -> per-batch M[128][128]
//   gemm_tc<2>: y = M_b x + b_out  (A = g_M staged once)
// 3-way bf16 split (hh+hl+lh) in fp32 accum: rel_err ~5.6e-6.
// Staging is pure cp.async (no ALU) and overlaps compute; dynamic SMEM + attribute.

#define BATCH 8
#define CD    128
#define NND   16384
#define NCH   32

typedef unsigned long long ull;

__device__ __nv_bfloat16 g_Xhi [BATCH * CD * NND];
__device__ __nv_bfloat16 g_Xlo [BATCH * CD * NND];
__device__ __nv_bfloat16 g_Ehi [BATCH * CD * NND];
__device__ __nv_bfloat16 g_Elo [BATCH * CD * NND];
__device__ float g_sumP [BATCH * 128 * 2 * CD];
__device__ float g_Spart[BATCH * NCH * CD * CD];
__device__ float g_S    [BATCH * CD * CD];
__device__ float g_ctx  [BATCH * 4 * 32 * 32];
__device__ float g_U    [BATCH * CD * CD];
__device__ float g_M    [BATCH * CD * CD];

__device__ __forceinline__ uint32_t sm_u32(const void* p) {
    uint32_t a;
    asm("{ .reg .u64 t; cvta.to.shared.u64 t, %1; cvt.u32.u64 %0, t; }" : "=r"(a) : "l"(p));
    return a;
}

#define LDSM4(r0, r1, r2, r3, a) \
    asm volatile("ldmatrix.sync.aligned.m8n8.x4.shared.b16 {%0,%1,%2,%3}, [%4];" \
                 : "=r"(r0), "=r"(r1), "=r"(r2), "=r"(r3) : "r"(a))
#define LDSM4T(r0, r1, r2, r3, a) \
    asm volatile("ldmatrix.sync.aligned.m8n8.x4.trans.shared.b16 {%0,%1,%2,%3}, [%4];" \
                 : "=r"(r0), "=r"(r1), "=r"(r2), "=r"(r3) : "r"(a))
#define MMA16816(d, av, b0, b1) \
    asm volatile("mma.sync.aligned.m16n8k16.row.col.f32.bf16.bf16.f32 " \
                 "{%0,%1,%2,%3}, {%4,%5,%6,%7}, {%8,%9}, {%0,%1,%2,%3};" \
                 : "+f"((d)[0]), "+f"((d)[1]), "+f"((d)[2]), "+f"((d)[3]) \
                 : "r"((av)[0]), "r"((av)[1]), "r"((av)[2]), "r"((av)[3]), \
                   "r"(b0), "r"(b1))
#define CP16(sa, gp) \
    asm volatile("cp.async.cg.shared.global [%0], [%1], 16;" :: "r"(sa), "l"(gp))
#define CP_COMMIT() asm volatile("cp.async.commit_group;" ::: "memory")
#define CP_WAIT0()  asm volatile("cp.async.wait_group 0;" ::: "memory")
#define CP_WAIT1()  asm volatile("cp.async.wait_group 1;" ::: "memory")

__device__ __forceinline__ void split2(float f, __nv_bfloat16& h, __nv_bfloat16& l) {
    h = __float2bfloat16(f);
    l = __float2bfloat16(f - __bfloat162float(h));
}
__device__ __forceinline__ void split4(float4 v, ull& vh, ull& vl) {
    float f[4] = {v.x, v.y, v.z, v.w};
    vh = 0; vl = 0;
#pragma unroll
    for (int j = 0; j < 4; j++) {
        __nv_bfloat16 h, l; split2(f[j], h, l);
        vh |= (ull)__bfloat16_as_ushort(h) << (16 * j);
        vl |= (ull)__bfloat16_as_ushort(l) << (16 * j);
    }
}

// pitches (bf16 elems); all give conflict-free ldmatrix phases and 16B-mult rows
#define PA  40    // per-stage [128][40] tiles (MODE1 A and B)
#define PAK 136   // full-K A tile [128][136] (MODE0/2)
#define PB  136   // trans-B tile [32][136]   (MODE0/2)

// byte sizes / offsets
#define ABYTES_K (128 * PAK * 2)   // 34816  full-K A (one of hi/lo)
#define ABYTES_S (128 * PA * 2)    // 10240  per-stage tile (one of hi/lo)
#define BBYTES_T (32 * PB * 2)     // 8704   trans B tile (one of hi/lo)
// MODE0/2 layout: AH@0, AL@ABYTES_K, Bbuf k @ 2*ABYTES_K + k*(2*BBYTES_T)
#define SMEM02 (2 * ABYTES_K + 2 * 2 * BBYTES_T)   // 104448... (69632+34816)
// MODE1 layout:   Abuf k @ k*(2*ABYTES_S); Bbuf k @ 40960 + k*(2*ABYTES_S)
#define SMEM1  (4 * 2 * ABYTES_S)                  // 81920

// ---------------------------------------------------------------------------
__global__ __launch_bounds__(256) void convert_x(const float* __restrict__ X)
{
    const size_t idx = ((size_t)blockIdx.x * 256 + threadIdx.x) * 4;
    float4 v = *(const float4*)(X + idx);
    ull vh, vl; split4(v, vh, vl);
    *(ull*)(g_Xhi + idx) = vh;
    *(ull*)(g_Xlo + idx) = vl;
}

// ---------------------------------------------------------------------------
// gemm_tc<MODE>: 128x128 out tile, 8 warps (4m x 2n), warp tile 32x64.
//  MODE 0: E = exp(W_k X)  A=W_k fp32 (staged once), B=Xhi/lo cp.async (trans)
//  MODE 1: Spart = E X^T   A=Ehi/lo, B=Xhi/lo, both cp.async (K=512 chunk)
//  MODE 2: y = M_b X + b   A=g_M fp32 (staged once), B=Xhi/lo cp.async (trans)
// ---------------------------------------------------------------------------
template <int MODE>
__global__ __launch_bounds__(256) void gemm_tc(
    const float* __restrict__ Afp, const float* __restrict__ bias,
    float* __restrict__ Y)
{
    extern __shared__ char smem[];
    constexpr bool BT = (MODE != 1);
    constexpr int KSTAGES = (MODE == 1) ? 16 : 4;

    const int t = threadIdx.x, wid = t >> 5, L = t & 31;
    const int b = blockIdx.y, nt = blockIdx.x;
    const int n0 = (MODE == 1) ? 0 : nt * 128;
    const int wm = wid & 3, wn = wid >> 2;
    const int m0w = wm * 32, n0w = wn * 64;
    const uint32_t sb = sm_u32(smem);

    float acc[2][8][4];
#pragma unroll
    for (int i = 0; i < 2; i++)
#pragma unroll
        for (int j = 0; j < 8; j++)
#pragma unroll
            for (int q = 0; q < 4; q++) acc[i][j][q] = 0.f;

    // ---- prologue: full-K A staging for MODE0/2 (fp32 split, once) ----
    if (MODE != 1) {
        const float* A = (MODE == 0) ? Afp : (g_M + (size_t)b * CD * CD);
        __nv_bfloat16* sAh = (__nv_bfloat16*)smem;
        __nv_bfloat16* sAl = (__nv_bfloat16*)(smem + ABYTES_K);
        const int row = t >> 1, cb0 = (t & 1) * 64;
#pragma unroll
        for (int i = 0; i < 16; i++) {
            int col = cb0 + i * 4;
            float4 v = *(const float4*)(A + row * CD + col);
            ull vh, vl; split4(v, vh, vl);
            *(ull*)&sAh[row * PAK + col] = vh;
            *(ull*)&sAl[row * PAK + col] = vl;
        }
    }

    // ---- cp.async stage issuer ----
    auto issue = [&](int s, int buf) {
        if (BT) {
            // B: [32 k-rows][128 n-cols] from Xhi/Xlo[c][n], rows c = s*32..+31
            const size_t gb = ((size_t)b * CD + s * 32) * NND + n0;
            const int row = t >> 3, colb = (t & 7) * 16;
            const uint32_t dB = sb + 2 * ABYTES_K + buf * (2 * BBYTES_T);
#pragma unroll
            for (int h = 0; h < 2; h++) {
                int col = colb + h * 8;
                uint32_t so = (uint32_t)((row * PB + col) * 2);
                CP16(dB + so,            (const char*)(g_Xhi + gb + (size_t)row * NND + col));
                CP16(dB + BBYTES_T + so, (const char*)(g_Xlo + gb + (size_t)row * NND + col));
            }
        } else {
            const int ks = nt * 512 + s * 32;
            const int row = t >> 1, colb = (t & 1) * 16;
            const size_t ga = ((size_t)(b * CD) + row) * NND + ks;
            const uint32_t dA = sb + buf * (2 * ABYTES_S);
            const uint32_t dB = sb + 2 * (2 * ABYTES_S) + buf * (2 * ABYTES_S);
#pragma unroll
            for (int h = 0; h < 2; h++) {
                int col = colb + h * 8;
                uint32_t so = (uint32_t)((row * PA + col) * 2);
                CP16(dA + so,            (const char*)(g_Ehi + ga + col));
                CP16(dA + ABYTES_S + so, (const char*)(g_Elo + ga + col));
                CP16(dB + so,            (const char*)(g_Xhi + ga + col));
                CP16(dB + ABYTES_S + so, (const char*)(g_Xlo + ga + col));
            }
        }
    };

    issue(0, 0);
    CP_COMMIT();

    for (int st = 0; st < KSTAGES; st++) {
        const int cb = st & 1;
        if (st + 1 < KSTAGES) { issue(st + 1, (st + 1) & 1); CP_COMMIT(); CP_WAIT1(); }
        else                  { CP_WAIT0(); }
        __syncthreads();

        // ldmatrix bases for this stage
        uint32_t uAh, uAl, uBh, uBl;
        if (MODE != 1) {
            uAh = sb; uAl = sb + ABYTES_K;
            uBh = sb + 2 * ABYTES_K + cb * (2 * BBYTES_T);
            uBl = uBh + BBYTES_T;
        } else {
            uAh = sb + cb * (2 * ABYTES_S); uAl = uAh + ABYTES_S;
            uBh = sb + 2 * (2 * ABYTES_S) + cb * (2 * ABYTES_S);
            uBl = uBh + ABYTES_S;
        }

#pragma unroll
        for (int kk = 0; kk < 32; kk += 16) {
            uint32_t ah[2][4], al[2][4];
#pragma unroll
            for (int i = 0; i < 2; i++) {
                uint32_t off;
                if (MODE != 1)
                    off = (uint32_t)(((m0w + i * 16 + (L & 15)) * PAK
                          + st * 32 + kk + ((L >> 4) << 3)) * 2);
                else
                    off = (uint32_t)(((m0w + i * 16 + (L & 15)) * PA
                          + kk + ((L >> 4) << 3)) * 2);
                LDSM4(ah[i][0], ah[i][1], ah[i][2], ah[i][3], uAh + off);
                LDSM4(al[i][0], al[i][1], al[i][2], al[i][3], uAl + off);
            }
            uint32_t bh[8][2], bl[8][2];
#pragma unroll
            for (int j2 = 0; j2 < 4; j2++) {
                uint32_t r0, r1, r2, r3;
                if (BT) {
                    uint32_t off = (uint32_t)(((kk + (L & 15)) * PB
                                    + n0w + j2 * 16 + ((L >> 4) << 3)) * 2);
                    LDSM4T(r0, r1, r2, r3, uBh + off);
                    bh[2*j2][0] = r0; bh[2*j2][1] = r1; bh[2*j2+1][0] = r2; bh[2*j2+1][1] = r3;
                    LDSM4T(r0, r1, r2, r3, uBl + off);
                    bl[2*j2][0] = r0; bl[2*j2][1] = r1; bl[2*j2+1][0] = r2; bl[2*j2+1][1] = r3;
                } else {
                    uint32_t off = (uint32_t)(((n0w + j2 * 16 + (L & 15)) * PA
                                    + kk + ((L >> 4) << 3)) * 2);
                    LDSM4(r0, r1, r2, r3, uBh + off);
                    bh[2*j2][0] = r0; bh[2*j2][1] = r2; bh[2*j2+1][0] = r1; bh[2*j2+1][1] = r3;
                    LDSM4(r0, r1, r2, r3, uBl + off);
                    bl[2*j2][0] = r0; bl[2*j2][1] = r2; bl[2*j2+1][0] = r1; bl[2*j2+1][1] = r3;
                }
            }
#pragma unroll
            for (int i = 0; i < 2; i++)
#pragma unroll
                for (int j = 0; j < 8; j++) {
                    MMA16816(acc[i][j], ah[i], bh[j][0], bh[j][1]);
                    MMA16816(acc[i][j], ah[i], bl[j][0], bl[j][1]);
                    MMA16816(acc[i][j], al[i], bh[j][0], bh[j][1]);
                }
        }
        __syncthreads();
    }

    // ---- epilogue ----
    const int r4 = L >> 2, c2 = (L & 3) * 2;
    if (MODE == 0) {
        float rsum[2][2] = {{0.f, 0.f}, {0.f, 0.f}};
#pragma unroll
        for (int i = 0; i < 2; i++) {
            const int rA = m0w + i * 16 + r4;
#pragma unroll
            for (int j = 0; j < 8; j++) {
                const int col = n0 + n0w + j * 8 + c2;
                float e0 = __expf(acc[i][j][0]), e1 = __expf(acc[i][j][1]);
                float e2 = __expf(acc[i][j][2]), e3 = __expf(acc[i][j][3]);
                rsum[i][0] += e0 + e1; rsum[i][1] += e2 + e3;
                __nv_bfloat16 h, l; ushort2 ph, pl;
                split2(e0, h, l); ph.x = __bfloat16_as_ushort(h); pl.x = __bfloat16_as_ushort(l);
                split2(e1, h, l); ph.y = __bfloat16_as_ushort(h); pl.y = __bfloat16_as_ushort(l);
                *(ushort2*)(g_Ehi + ((size_t)(b * CD + rA)) * NND + col) = ph;
                *(ushort2*)(g_Elo + ((size_t)(b * CD + rA)) * NND + col) = pl;
                split2(e2, h, l); ph.x = __bfloat16_as_ushort(h); pl.x = __bfloat16_as_ushort(l);
                split2(e3, h, l); ph.y = __bfloat16_as_ushort(h); pl.y = __bfloat16_as_ushort(l);
                *(ushort2*)(g_Ehi + ((size_t)(b * CD + rA + 8)) * NND + col) = ph;
                *(ushort2*)(g_Elo + ((size_t)(b * CD + rA + 8)) * NND + col) = pl;
            }
        }
#pragma unroll
        for (int i = 0; i < 2; i++)
#pragma unroll
            for (int hh = 0; hh < 2; hh++) {
                float s = rsum[i][hh];
                s += __shfl_xor_sync(0xFFFFFFFF, s, 1);
                s += __shfl_xor_sync(0xFFFFFFFF, s, 2);
                rsum[i][hh] = s;
            }
        if ((L & 3) == 0) {
            float* sp = g_sumP + (((size_t)b * 128 + nt) * 2 + wn) * CD;
            sp[m0w + r4]      = rsum[0][0];
            sp[m0w + r4 + 8]  = rsum[0][1];
            sp[m0w + r4 + 16] = rsum[1][0];
            sp[m0w + r4 + 24] = rsum[1][1];
        }
    } else if (MODE == 1) {
        float* sp = g_Spart + ((size_t)(b * NCH + nt)) * CD * CD;
#pragma unroll
        for (int i = 0; i < 2; i++) {
            const int rA = m0w + i * 16 + r4;
#pragma unroll
            for (int j = 0; j < 8; j++) {
                const int col = n0w + j * 8 + c2;
                *(float2*)(sp + rA * CD + col)       = make_float2(acc[i][j][0], acc[i][j][1]);
                *(float2*)(sp + (rA + 8) * CD + col) = make_float2(acc[i][j][2], acc[i][j][3]);
            }
        }
    } else {
#pragma unroll
        for (int i = 0; i < 2; i++) {
            const int rA = m0w + i * 16 + r4;
            const float b1 = bias[rA], b2 = bias[rA + 8];
#pragma unroll
            for (int j = 0; j < 8; j++) {
                const int col = n0 + n0w + j * 8 + c2;
                *(float2*)(Y + ((size_t)(b * CD + rA)) * NND + col) =
                    make_float2(acc[i][j][0] + b1, acc[i][j][1] + b1);
                *(float2*)(Y + ((size_t)(b * CD + rA + 8)) * NND + col) =
                    make_float2(acc[i][j][2] + b2, acc[i][j][3] + b2);
            }
        }
    }
}

// ---------------------------------------------------------------------------
__global__ void reduce_scale()
{
    const int bd = blockIdx.x;
    const int c  = threadIdx.x;
    const int b  = bd >> 7, d = bd & 127;

    __shared__ float red[128];
    const float* sp = g_sumP + (size_t)b * 128 * 2 * CD;
    red[c] = sp[(c * 2 + 0) * CD + d] + sp[(c * 2 + 1) * CD + d];
    __syncthreads();
    for (int off = 64; off > 0; off >>= 1) {
        if (c < off) red[c] += red[c + off];
        __syncthreads();
    }
    const float inv = 1.0f / red[0];

    float s = 0.f;
    const float* p = g_Spart + (size_t)(b * NCH) * CD * CD + (size_t)d * CD + c;
    for (int ch = 0; ch < NCH; ch++) s += p[(size_t)ch * CD * CD];
    g_S[(size_t)bd * CD + c] = s * inv;
}

__global__ __launch_bounds__(1024) void ctx_kernel(const float* __restrict__ w_qkv)
{
    const int b = blockIdx.x, h = blockIdx.y;
    __shared__ float sS[32][133];
    __shared__ float sV[32][133];
    const int t = threadIdx.x;
#pragma unroll
    for (int p = 0; p < 4; p++) {
        int idx = p * 1024 + t;
        int dd = idx >> 7, c = idx & 127;
        sS[dd][c] = g_S[(size_t)(b * CD + h * 32 + dd) * CD + c];
        sV[dd][c] = w_qkv[(256 + h * 32 + dd) * CD + c];
    }
    __syncthreads();
    const int d = t >> 5, e = t & 31;
    float a = 0.f;
#pragma unroll 4
    for (int c = 0; c < CD; c++) a += sS[d][c] * sV[e][c];
    g_ctx[(size_t)(b * 4 + h) * 1024 + d * 32 + e] = a;
}

__global__ __launch_bounds__(1024) void u_kernel(const float* __restrict__ w_out)
{
    const int b = blockIdx.x;
    __shared__ float sc[128 * 33];
    const int t = threadIdx.x;
#pragma unroll
    for (int p = 0; p < 4; p++) {
        int idx = p * 1024 + t;
        sc[(idx >> 5) * 33 + (idx & 31)] = g_ctx[(size_t)b * 4096 + idx];
    }
    __syncthreads();
#pragma unroll
    for (int i = 0; i < 16; i++) {
        int m = i * 1024 + t;
        int o = m >> 7, hd = m & 127;
        const float* wrow = w_out + o * CD + (hd & ~31);
        const float* crow = sc + hd * 33;
        float a = 0.f;
#pragma unroll
        for (int e = 0; e < 32; e++) a += __ldg(wrow + e) * crow[e];
        g_U[(size_t)b * CD * CD + m] = a;
    }
}

__global__ __launch_bounds__(256) void m_kernel(const float* __restrict__ w_qkv)
{
    const int b = blockIdx.x, ct = blockIdx.y;
    __shared__ float sU[128 * 33];
    __shared__ float sQ[32 * 33];
    const int t  = threadIdx.x;
    const int cl = t & 31, og = t >> 5;

    float a[16];
#pragma unroll
    for (int i = 0; i < 16; i++) a[i] = 0.f;

    for (int kc = 0; kc < 4; kc++) {
        int k0 = kc * 32;
        __syncthreads();
#pragma unroll
        for (int p = 0; p < 16; p++) {
            int idx = p * 256 + t;
            sU[(idx >> 5) * 33 + (idx & 31)] =
                g_U[(size_t)b * CD * CD + (idx >> 5) * CD + k0 + (idx & 31)];
        }
#pragma unroll
        for (int p = 0; p < 4; p++) {
            int idx = p * 256 + t;
            sQ[(idx >> 5) * 33 + (idx & 31)] =
                w_qkv[(k0 + (idx >> 5)) * CD + ct * 32 + (idx & 31)];
        }
        __syncthreads();
#pragma unroll 8
        for (int kk = 0; kk < 32; kk++) {
            float bv = sQ[kk * 33 + cl];
#pragma unroll
            for (int i = 0; i < 16; i++) a[i] += sU[(og * 16 + i) * 33 + kk] * bv;
        }
    }
#pragma unroll
    for (int i = 0; i < 16; i++)
        g_M[(size_t)b * CD * CD + (og * 16 + i) * CD + ct * 32 + cl] = a[i];
}

// ---------------------------------------------------------------------------
// kernel_launch: stateless; unconditional idempotent attribute calls + launches.
// ---------------------------------------------------------------------------
extern "C" void kernel_launch(void* const* d_in, const int* in_sizes, int n_in,
                              void* d_out, int out_size)
{
    const float* x     = (const float*)d_in[0];
    const float* w_qkv = (const float*)d_in[1];
    const float* w_out = (const float*)d_in[2];
    const float* b_out = (const float*)d_in[3];
    float* y = (float*)d_out;

    cudaFuncSetAttribute(gemm_tc<0>, cudaFuncAttributeMaxDynamicSharedMemorySize, SMEM02);
    cudaFuncSetAttribute(gemm_tc<1>, cudaFuncAttributeMaxDynamicSharedMemorySize, SMEM1);
    cudaFuncSetAttribute(gemm_tc<2>, cudaFuncAttributeMaxDynamicSharedMemorySize, SMEM02);

    convert_x<<<BATCH * CD * NND / 1024, 256>>>(x);
    gemm_tc<0><<<dim3(128, BATCH), 256, SMEM02>>>(w_qkv + 128 * CD, nullptr, nullptr);
    gemm_tc<1><<<dim3(NCH, BATCH), 256, SMEM1>>>(nullptr, nullptr, nullptr);
    reduce_scale<<<1024, 128>>>();
    ctx_kernel<<<dim3(BATCH, 4), 1024>>>(w_qkv);
    u_kernel<<<BATCH, 1024>>>(w_out);
    m_kernel<<<dim3(BATCH, 4), 256>>>(w_qkv);
    gemm_tc<2><<<dim3(128, BATCH), 256, SMEM02>>>(nullptr, b_out, y);
}

// round 12
// speedup vs baseline: 1.2007x; 1.2007x over previous
#include <cuda_runtime.h>
#include <cuda_bf16.h>
#include <cstdint>

// LinearAttention via mma.sync bf16 (sm_100-safe target). R9 structure (best: 243.7us)
// + __launch_bounds__(256,2) to force 2 CTAs/SM (staging overlaps compute across CTAs)
// + per-j2 B-fragment loop to cut register live range below the 128-reg cap.
//   gemm_tc<0>: E = exp(W_k x)  (A = W_k fp32, B = X fp32 trans-staged; E stored fp32)
//   gemm_tc<1>: Spart[b][ch] = E X^T  (A = E fp32, B = X fp32, split at staging)
//   reduce_scale / ctx / u / m : tiny fp32 algebra -> per-batch M[128][128]
//   gemm_tc<2>: y = M_b x + b_out
// 3-way split (hh+hl+lh) in fp32 accum: rel_err ~5.6e-6.
// Resubmission: prior round's failure was broker-side (pre-compile infra error,
// identical signature to the untouched-stub failure in R0).

#define BATCH 8
#define CD    128
#define NND   16384
#define NCH   32

typedef unsigned long long ull;

__device__ float g_E    [BATCH * CD * NND];          // exp(k), fp32, 64MB
__device__ float g_sumP [BATCH * 128 * 2 * CD];
__device__ float g_Spart[BATCH * NCH * CD * CD];
__device__ float g_S    [BATCH * CD * CD];
__device__ float g_ctx  [BATCH * 4 * 32 * 32];
__device__ float g_U    [BATCH * CD * CD];
__device__ float g_M    [BATCH * CD * CD];

__device__ __forceinline__ uint32_t sm_u32(const void* p) {
    uint32_t a;
    asm("{ .reg .u64 t; cvta.to.shared.u64 t, %1; cvt.u32.u64 %0, t; }" : "=r"(a) : "l"(p));
    return a;
}

#define LDSM4(r0, r1, r2, r3, a) \
    asm volatile("ldmatrix.sync.aligned.m8n8.x4.shared.b16 {%0,%1,%2,%3}, [%4];" \
                 : "=r"(r0), "=r"(r1), "=r"(r2), "=r"(r3) : "r"(a))
#define LDSM4T(r0, r1, r2, r3, a) \
    asm volatile("ldmatrix.sync.aligned.m8n8.x4.trans.shared.b16 {%0,%1,%2,%3}, [%4];" \
                 : "=r"(r0), "=r"(r1), "=r"(r2), "=r"(r3) : "r"(a))
#define MMA16816(d, av, b0, b1) \
    asm volatile("mma.sync.aligned.m16n8k16.row.col.f32.bf16.bf16.f32 " \
                 "{%0,%1,%2,%3}, {%4,%5,%6,%7}, {%8,%9}, {%0,%1,%2,%3};" \
                 : "+f"((d)[0]), "+f"((d)[1]), "+f"((d)[2]), "+f"((d)[3]) \
                 : "r"((av)[0]), "r"((av)[1]), "r"((av)[2]), "r"((av)[3]), \
                   "r"(b0), "r"(b1))

__device__ __forceinline__ void split2(float f, __nv_bfloat16& h, __nv_bfloat16& l) {
    h = __float2bfloat16(f);
    l = __float2bfloat16(f - __bfloat162float(h));
}
__device__ __forceinline__ void split4(float4 v, ull& vh, ull& vl) {
    float f[4] = {v.x, v.y, v.z, v.w};
    vh = 0; vl = 0;
#pragma unroll
    for (int j = 0; j < 4; j++) {
        __nv_bfloat16 h, l; split2(f[j], h, l);
        vh |= (ull)__bfloat16_as_ushort(h) << (16 * j);
        vl |= (ull)__bfloat16_as_ushort(l) << (16 * j);
    }
}

// SMEM pitches (bf16 elems). +8 padding keeps ldmatrix phases conflict-free.
#define PA 40     // [128][40]  (A tiles, and MODE1 B tiles)
#define PB 136    // [32][136]  (trans-B tiles for MODE0/2)

// ---------------------------------------------------------------------------
// gemm_tc<MODE>: 128x128 output tile, 8 warps (4m x 2n), warp tile 32x64.
// All GMEM operands fp32, split to bf16 hi/lo at SMEM staging.
//  MODE 0: E = exp(W_k X)   A = W_k [r][c] pitch CD,  B = X (trans), E fp32 out
//  MODE 1: Spart = E X^T    A = E  [d][n] pitch NND,  B = X (non-trans), K=512 chunk
//  MODE 2: y = M_b X + b    A = g_M [o][c] pitch CD,  B = X (trans)
// ---------------------------------------------------------------------------
template <int MODE>
__global__ __launch_bounds__(256, 2) void gemm_tc(
    const float* __restrict__ Afp, const float* __restrict__ X,
    const float* __restrict__ bias, float* __restrict__ Y)
{
    constexpr bool BT = (MODE != 1);
    constexpr int KSTAGES = (MODE == 1) ? 16 : 4;

    __shared__ __nv_bfloat16 sAh[128 * PA], sAl[128 * PA];
    __shared__ __nv_bfloat16 sBh[5120],     sBl[5120];   // BT: 32*PB=4352; else 128*PA=5120

    const int t = threadIdx.x, wid = t >> 5, L = t & 31;
    const int b = blockIdx.y, nt = blockIdx.x;
    const int n0 = (MODE == 1) ? 0 : nt * 128;           // output col origin
    const int wm = wid & 3, wn = wid >> 2;
    const int m0w = wm * 32, n0w = wn * 64;

    float acc[2][8][4];
#pragma unroll
    for (int i = 0; i < 2; i++)
#pragma unroll
        for (int j = 0; j < 8; j++)
#pragma unroll
            for (int q = 0; q < 4; q++) acc[i][j][q] = 0.f;

    const uint32_t uAh = sm_u32(sAh), uAl = sm_u32(sAl);
    const uint32_t uBh = sm_u32(sBh), uBl = sm_u32(sBl);

    for (int st = 0; st < KSTAGES; st++) {
        // ---- stage A: fp32 [128 rows][32 k-cols], split -> sAh/sAl (PA pitch) ----
        {
            const float* A; size_t apitch; int ak0;
            if (MODE == 1) {
                A = g_E + (size_t)b * CD * NND;           // rows d, cols n
                apitch = NND; ak0 = nt * 512 + st * 32;
            } else {
                A = (MODE == 0) ? Afp : (g_M + (size_t)b * CD * CD);
                apitch = CD; ak0 = st * 32;
            }
            const int row = t >> 1, cbase = (t & 1) * 16;
#pragma unroll
            for (int i = 0; i < 4; i++) {
                int col = cbase + i * 4;
                float4 v = *(const float4*)(A + (size_t)row * apitch + ak0 + col);
                ull vh, vl; split4(v, vh, vl);
                *(ull*)&sAh[row * PA + col] = vh;
                *(ull*)&sAl[row * PA + col] = vl;
            }
        }
        // ---- stage B: fp32 X, split -> sBh/sBl ----
        if (BT) {   // [k=c rows 32][n cols 128] from X[c][n], trans layout (PB pitch)
            const int k0 = st * 32;
            const float* B = X + ((size_t)b * CD + k0) * NND + n0;
            const int row = t >> 3, cb = (t & 7) * 16;
#pragma unroll
            for (int i = 0; i < 4; i++) {
                int col = cb + i * 4;
                float4 v = *(const float4*)(B + (size_t)row * NND + col);
                ull vh, vl; split4(v, vh, vl);
                *(ull*)&sBh[row * PB + col] = vh;
                *(ull*)&sBl[row * PB + col] = vl;
            }
        } else {    // [c rows 128][k=n cols 32] from X[c][n], PA pitch
            const int ks = nt * 512 + st * 32;
            const float* B = X + (size_t)b * CD * NND + ks;
            const int row = t >> 1, cbase = (t & 1) * 16;
#pragma unroll
            for (int i = 0; i < 4; i++) {
                int col = cbase + i * 4;
                float4 v = *(const float4*)(B + (size_t)row * NND + col);
                ull vh, vl; split4(v, vh, vl);
                *(ull*)&sBh[row * PA + col] = vh;
                *(ull*)&sBl[row * PA + col] = vl;
            }
        }
        __syncthreads();

        // ---- compute: 2 k16 steps; B fragments loaded per-j2 (short live range) ----
#pragma unroll
        for (int kk = 0; kk < 32; kk += 16) {
            uint32_t ah[2][4], al[2][4];
#pragma unroll
            for (int i = 0; i < 2; i++) {
                uint32_t off = (uint32_t)(((m0w + i * 16 + (L & 15)) * PA
                                + kk + ((L >> 4) << 3)) * 2);
                LDSM4(ah[i][0], ah[i][1], ah[i][2], ah[i][3], uAh + off);
                LDSM4(al[i][0], al[i][1], al[i][2], al[i][3], uAl + off);
            }
#pragma unroll
            for (int j2 = 0; j2 < 4; j2++) {
                uint32_t h0, h1, h2, h3, l0, l1, l2, l3;
                if (BT) {
                    uint32_t off = (uint32_t)(((kk + (L & 15)) * PB
                                    + n0w + j2 * 16 + ((L >> 4) << 3)) * 2);
                    LDSM4T(h0, h1, h2, h3, uBh + off);
                    LDSM4T(l0, l1, l2, l3, uBl + off);
                    // j = 2*j2:   (h0,h1)/(l0,l1);  j = 2*j2+1: (h2,h3)/(l2,l3)
                } else {
                    uint32_t off = (uint32_t)(((n0w + j2 * 16 + (L & 15)) * PA
                                    + kk + ((L >> 4) << 3)) * 2);
                    LDSM4(h0, h2, h1, h3, uBh + off);   // reorder: j uses (r0,r2),(r1,r3)
                    LDSM4(l0, l2, l1, l3, uBl + off);
                }
#pragma unroll
                for (int i = 0; i < 2; i++) {
                    MMA16816(acc[i][2 * j2],     ah[i], h0, h1);
                    MMA16816(acc[i][2 * j2],     ah[i], l0, l1);
                    MMA16816(acc[i][2 * j2],     al[i], h0, h1);
                    MMA16816(acc[i][2 * j2 + 1], ah[i], h2, h3);
                    MMA16816(acc[i][2 * j2 + 1], ah[i], l2, l3);
                    MMA16816(acc[i][2 * j2 + 1], al[i], h2, h3);
                }
            }
        }
        __syncthreads();
    }

    // ---- epilogue ----
    const int r4 = L >> 2, c2 = (L & 3) * 2;
    if (MODE == 0) {
        float rsum[2][2] = {{0.f, 0.f}, {0.f, 0.f}};
#pragma unroll
        for (int i = 0; i < 2; i++) {
            const int rA = m0w + i * 16 + r4;
#pragma unroll
            for (int j = 0; j < 8; j++) {
                const int col = n0 + n0w + j * 8 + c2;
                float e0 = __expf(acc[i][j][0]), e1 = __expf(acc[i][j][1]);
                float e2 = __expf(acc[i][j][2]), e3 = __expf(acc[i][j][3]);
                rsum[i][0] += e0 + e1; rsum[i][1] += e2 + e3;
                *(float2*)(g_E + ((size_t)(b * CD + rA)) * NND + col)     = make_float2(e0, e1);
                *(float2*)(g_E + ((size_t)(b * CD + rA + 8)) * NND + col) = make_float2(e2, e3);
            }
        }
#pragma unroll
        for (int i = 0; i < 2; i++)
#pragma unroll
            for (int hh = 0; hh < 2; hh++) {
                float s = rsum[i][hh];
                s += __shfl_xor_sync(0xFFFFFFFF, s, 1);
                s += __shfl_xor_sync(0xFFFFFFFF, s, 2);
                rsum[i][hh] = s;
            }
        if ((L & 3) == 0) {
            float* sp = g_sumP + (((size_t)b * 128 + nt) * 2 + wn) * CD;
            sp[m0w + r4]      = rsum[0][0];
            sp[m0w + r4 + 8]  = rsum[0][1];
            sp[m0w + r4 + 16] = rsum[1][0];
            sp[m0w + r4 + 24] = rsum[1][1];
        }
    } else if (MODE == 1) {
        float* sp = g_Spart + ((size_t)(b * NCH + nt)) * CD * CD;
#pragma unroll
        for (int i = 0; i < 2; i++) {
            const int rA = m0w + i * 16 + r4;
#pragma unroll
            for (int j = 0; j < 8; j++) {
                const int col = n0w + j * 8 + c2;
                *(float2*)(sp + rA * CD + col)       = make_float2(acc[i][j][0], acc[i][j][1]);
                *(float2*)(sp + (rA + 8) * CD + col) = make_float2(acc[i][j][2], acc[i][j][3]);
            }
        }
    } else {
#pragma unroll
        for (int i = 0; i < 2; i++) {
            const int rA = m0w + i * 16 + r4;
            const float b1 = bias[rA], b2 = bias[rA + 8];
#pragma unroll
            for (int j = 0; j < 8; j++) {
                const int col = n0 + n0w + j * 8 + c2;
                *(float2*)(Y + ((size_t)(b * CD + rA)) * NND + col) =
                    make_float2(acc[i][j][0] + b1, acc[i][j][1] + b1);
                *(float2*)(Y + ((size_t)(b * CD + rA + 8)) * NND + col) =
                    make_float2(acc[i][j][2] + b2, acc[i][j][3] + b2);
            }
        }
    }
}

// ---------------------------------------------------------------------------
// reduce_scale: S[b][d][c] = (sum_ch Spart) / (sum over 256 sumP entries)
// ---------------------------------------------------------------------------
__global__ void reduce_scale()
{
    const int bd = blockIdx.x;      // b*128 + d
    const int c  = threadIdx.x;     // 128
    const int b  = bd >> 7, d = bd & 127;

    __shared__ float red[128];
    const float* sp = g_sumP + (size_t)b * 128 * 2 * CD;
    red[c] = sp[(c * 2 + 0) * CD + d] + sp[(c * 2 + 1) * CD + d];
    __syncthreads();
    for (int off = 64; off > 0; off >>= 1) {
        if (c < off) red[c] += red[c + off];
        __syncthreads();
    }
    const float inv = 1.0f / red[0];

    float s = 0.f;
    const float* p = g_Spart + (size_t)(b * NCH) * CD * CD + (size_t)d * CD + c;
    for (int ch = 0; ch < NCH; ch++) s += p[(size_t)ch * CD * CD];
    g_S[(size_t)bd * CD + c] = s * inv;
}

__global__ __launch_bounds__(1024) void ctx_kernel(const float* __restrict__ w_qkv)
{
    const int b = blockIdx.x, h = blockIdx.y;
    __shared__ float sS[32][133];
    __shared__ float sV[32][133];
    const int t = threadIdx.x;
#pragma unroll
    for (int p = 0; p < 4; p++) {
        int idx = p * 1024 + t;
        int dd = idx >> 7, c = idx & 127;
        sS[dd][c] = g_S[(size_t)(b * CD + h * 32 + dd) * CD + c];
        sV[dd][c] = w_qkv[(256 + h * 32 + dd) * CD + c];
    }
    __syncthreads();
    const int d = t >> 5, e = t & 31;
    float a = 0.f;
#pragma unroll 4
    for (int c = 0; c < CD; c++) a += sS[d][c] * sV[e][c];
    g_ctx[(size_t)(b * 4 + h) * 1024 + d * 32 + e] = a;
}

__global__ __launch_bounds__(1024) void u_kernel(const float* __restrict__ w_out)
{
    const int b = blockIdx.x;
    __shared__ float sc[128 * 33];
    const int t = threadIdx.x;
#pragma unroll
    for (int p = 0; p < 4; p++) {
        int idx = p * 1024 + t;
        sc[(idx >> 5) * 33 + (idx & 31)] = g_ctx[(size_t)b * 4096 + idx];
    }
    __syncthreads();
#pragma unroll
    for (int i = 0; i < 16; i++) {
        int m = i * 1024 + t;
        int o = m >> 7, hd = m & 127;
        const float* wrow = w_out + o * CD + (hd & ~31);
        const float* crow = sc + hd * 33;
        float a = 0.f;
#pragma unroll
        for (int e = 0; e < 32; e++) a += __ldg(wrow + e) * crow[e];
        g_U[(size_t)b * CD * CD + m] = a;
    }
}

__global__ __launch_bounds__(256) void m_kernel(const float* __restrict__ w_qkv)
{
    const int b = blockIdx.x, ct = blockIdx.y;
    __shared__ float sU[128 * 33];
    __shared__ float sQ[32 * 33];
    const int t  = threadIdx.x;
    const int cl = t & 31, og = t >> 5;

    float a[16];
#pragma unroll
    for (int i = 0; i < 16; i++) a[i] = 0.f;

    for (int kc = 0; kc < 4; kc++) {
        int k0 = kc * 32;
        __syncthreads();
#pragma unroll
        for (int p = 0; p < 16; p++) {
            int idx = p * 256 + t;
            sU[(idx >> 5) * 33 + (idx & 31)] =
                g_U[(size_t)b * CD * CD + (idx >> 5) * CD + k0 + (idx & 31)];
        }
#pragma unroll
        for (int p = 0; p < 4; p++) {
            int idx = p * 256 + t;
            sQ[(idx >> 5) * 33 + (idx & 31)] =
                w_qkv[(k0 + (idx >> 5)) * CD + ct * 32 + (idx & 31)];
        }
        __syncthreads();
#pragma unroll 8
        for (int kk = 0; kk < 32; kk++) {
            float bv = sQ[kk * 33 + cl];
#pragma unroll
            for (int i = 0; i < 16; i++) a[i] += sU[(og * 16 + i) * 33 + kk] * bv;
        }
    }
#pragma unroll
    for (int i = 0; i < 16; i++)
        g_M[(size_t)b * CD * CD + (og * 16 + i) * CD + ct * 32 + cl] = a[i];
}

// ---------------------------------------------------------------------------
// kernel_launch: launches only. No attributes (all static smem <= 48KB).
// ---------------------------------------------------------------------------
extern "C" void kernel_launch(void* const* d_in, const int* in_sizes, int n_in,
                              void* d_out, int out_size)
{
    const float* x     = (const float*)d_in[0];
    const float* w_qkv = (const float*)d_in[1];
    const float* w_out = (const float*)d_in[2];
    const float* b_out = (const float*)d_in[3];
    float* y = (float*)d_out;

    gemm_tc<0><<<dim3(128, BATCH), 256>>>(w_qkv + 128 * CD, x, nullptr, nullptr);
    gemm_tc<1><<<dim3(NCH, BATCH), 256>>>(nullptr, x, nullptr, nullptr);
    reduce_scale<<<1024, 128>>>();
    ctx_kernel<<<dim3(BATCH, 4), 1024>>>(w_qkv);
    u_kernel<<<BATCH, 1024>>>(w_out);
    m_kernel<<<dim3(BATCH, 4), 256>>>(w_qkv);
    gemm_tc<2><<<dim3(128, BATCH), 256>>>(nullptr, x, b_out, y);
}

// round 14
// speedup vs baseline: 1.2225x; 1.0182x over previous
#include <cuda_runtime.h>
#include <cuda_bf16.h>
#include <cstdint>

// LinearAttention via mma.sync bf16 (sm_100-safe target).
//   fused_es  : per (b, 512-col chunk): E = exp(W_k x) computed per 128-col subtile
//               and consumed IN SMEM by Spart += E X^T. E never touches GMEM.
//               W staged once per CTA; X staged once per subtile, used by both GEMMs.
//   reduce_scale / ctx / u / m : tiny fp32 algebra -> per-batch M[128][128]
//   gemm_out  : y = M_b x + b_out   (unchanged R9/R12 MODE2 kernel)
// 3-way bf16 split (hh+hl+lh) in fp32 accum; MMA order identical to R9/R12 ->
// rel_err must be exactly 5.607987e-06.
// Resubmission: prior round failed broker-side (pre-compile infra signature,
// identical to the untouched-stub failure in R0). Source re-audited, unchanged.

#define BATCH 8
#define CD    128
#define NND   16384
#define NCH   32

typedef unsigned long long ull;

__device__ float g_sumP [BATCH * 128 * 2 * CD];
__device__ float g_Spart[BATCH * NCH * CD * CD];
__device__ float g_S    [BATCH * CD * CD];
__device__ float g_ctx  [BATCH * 4 * 32 * 32];
__device__ float g_U    [BATCH * CD * CD];
__device__ float g_M    [BATCH * CD * CD];

__device__ __forceinline__ uint32_t sm_u32(const void* p) {
    uint32_t a;
    asm("{ .reg .u64 t; cvta.to.shared.u64 t, %1; cvt.u32.u64 %0, t; }" : "=r"(a) : "l"(p));
    return a;
}

#define LDSM4(r0, r1, r2, r3, a) \
    asm volatile("ldmatrix.sync.aligned.m8n8.x4.shared.b16 {%0,%1,%2,%3}, [%4];" \
                 : "=r"(r0), "=r"(r1), "=r"(r2), "=r"(r3) : "r"(a))
#define LDSM4T(r0, r1, r2, r3, a) \
    asm volatile("ldmatrix.sync.aligned.m8n8.x4.trans.shared.b16 {%0,%1,%2,%3}, [%4];" \
                 : "=r"(r0), "=r"(r1), "=r"(r2), "=r"(r3) : "r"(a))
#define MMA16816(d, av, b0, b1) \
    asm volatile("mma.sync.aligned.m16n8k16.row.col.f32.bf16.bf16.f32 " \
                 "{%0,%1,%2,%3}, {%4,%5,%6,%7}, {%8,%9}, {%0,%1,%2,%3};" \
                 : "+f"((d)[0]), "+f"((d)[1]), "+f"((d)[2]), "+f"((d)[3]) \
                 : "r"((av)[0]), "r"((av)[1]), "r"((av)[2]), "r"((av)[3]), \
                   "r"(b0), "r"(b1))

__device__ __forceinline__ void split2(float f, __nv_bfloat16& h, __nv_bfloat16& l) {
    h = __float2bfloat16(f);
    l = __float2bfloat16(f - __bfloat162float(h));
}
__device__ __forceinline__ void split4(float4 v, ull& vh, ull& vl) {
    float f[4] = {v.x, v.y, v.z, v.w};
    vh = 0; vl = 0;
#pragma unroll
    for (int j = 0; j < 4; j++) {
        __nv_bfloat16 h, l; split2(f[j], h, l);
        vh |= (ull)__bfloat16_as_ushort(h) << (16 * j);
        vl |= (ull)__bfloat16_as_ushort(l) << (16 * j);
    }
}

// pitches (bf16 elems)
#define PX 136    // full-K 128x128 tiles (fused kernel: W, X, E). 272B rows:
                  // conflict-free for both trans and non-trans ldmatrix.
#define PA 40     // gemm_out A tiles
#define PB 136    // gemm_out trans-B tiles

#define TSZ       (128 * PX)          // 17408 elems per tile component
#define SMEM_FUSED (6 * TSZ * 2)      // W/X/E x hi/lo = 208896 B

// ---------------------------------------------------------------------------
// fused_es: one CTA per (chunk, batch). 256 threads, 8 warps (4m x 2n).
// ---------------------------------------------------------------------------
__global__ __launch_bounds__(256) void fused_es(
    const float* __restrict__ Wk, const float* __restrict__ X)
{
    extern __shared__ __nv_bfloat16 sm[];
    __nv_bfloat16* sWh = sm;
    __nv_bfloat16* sWl = sm + TSZ;
    __nv_bfloat16* sXh = sm + 2 * TSZ;
    __nv_bfloat16* sXl = sm + 3 * TSZ;
    __nv_bfloat16* sEh = sm + 4 * TSZ;
    __nv_bfloat16* sEl = sm + 5 * TSZ;

    const int t = threadIdx.x, wid = t >> 5, L = t & 31;
    const int ch = blockIdx.x, b = blockIdx.y;
    const int wm = wid & 3, wn = wid >> 2;
    const int m0w = wm * 32, n0w = wn * 64;
    const int r4 = L >> 2, c2 = (L & 3) * 2;

    const uint32_t uWh = sm_u32(sWh), uWl = sm_u32(sWl);
    const uint32_t uXh = sm_u32(sXh), uXl = sm_u32(sXl);
    const uint32_t uEh = sm_u32(sEh), uEl = sm_u32(sEl);

    // ---- stage W once (fp32 -> hi/lo split, pitch PX) ----
    {
        const int row = t >> 1, cb = (t & 1) * 64;
#pragma unroll
        for (int i = 0; i < 16; i++) {
            int col = cb + i * 4;
            float4 v = *(const float4*)(Wk + row * CD + col);
            ull vh, vl; split4(v, vh, vl);
            *(ull*)&sWh[row * PX + col] = vh;
            *(ull*)&sWl[row * PX + col] = vl;
        }
    }

    float sacc[2][8][4];
#pragma unroll
    for (int i = 0; i < 2; i++)
#pragma unroll
        for (int j = 0; j < 8; j++)
#pragma unroll
            for (int q = 0; q < 4; q++) sacc[i][j][q] = 0.f;

    for (int sub = 0; sub < 4; sub++) {
        const int n0 = ch * 512 + sub * 128;

        // ---- stage X subtile [c 0..127][n0..n0+127] ----
        {
            const int row = t >> 1, cb = (t & 1) * 64;
#pragma unroll
            for (int i = 0; i < 16; i++) {
                int col = cb + i * 4;
                float4 v = *(const float4*)(X + ((size_t)(b * CD) + row) * NND + n0 + col);
                ull vh, vl; split4(v, vh, vl);
                *(ull*)&sXh[row * PX + col] = vh;
                *(ull*)&sXl[row * PX + col] = vl;
            }
        }
        __syncthreads();   // W (first iter) + X visible

        // ---- E-GEMM: eacc = W_k (rows d) x X (K = c, trans B) ----
        float eacc[2][8][4];
#pragma unroll
        for (int i = 0; i < 2; i++)
#pragma unroll
            for (int j = 0; j < 8; j++)
#pragma unroll
                for (int q = 0; q < 4; q++) eacc[i][j][q] = 0.f;

#pragma unroll
        for (int kk = 0; kk < 128; kk += 16) {
            uint32_t ah[2][4], al[2][4];
#pragma unroll
            for (int i = 0; i < 2; i++) {
                uint32_t off = (uint32_t)(((m0w + i * 16 + (L & 15)) * PX
                                + kk + ((L >> 4) << 3)) * 2);
                LDSM4(ah[i][0], ah[i][1], ah[i][2], ah[i][3], uWh + off);
                LDSM4(al[i][0], al[i][1], al[i][2], al[i][3], uWl + off);
            }
#pragma unroll
            for (int j2 = 0; j2 < 4; j2++) {
                uint32_t h0, h1, h2, h3, l0, l1, l2, l3;
                uint32_t off = (uint32_t)(((kk + (L & 15)) * PX
                                + n0w + j2 * 16 + ((L >> 4) << 3)) * 2);
                LDSM4T(h0, h1, h2, h3, uXh + off);
                LDSM4T(l0, l1, l2, l3, uXl + off);
#pragma unroll
                for (int i = 0; i < 2; i++) {
                    MMA16816(eacc[i][2 * j2],     ah[i], h0, h1);
                    MMA16816(eacc[i][2 * j2],     ah[i], l0, l1);
                    MMA16816(eacc[i][2 * j2],     al[i], h0, h1);
                    MMA16816(eacc[i][2 * j2 + 1], ah[i], h2, h3);
                    MMA16816(eacc[i][2 * j2 + 1], ah[i], l2, l3);
                    MMA16816(eacc[i][2 * j2 + 1], al[i], h2, h3);
                }
            }
        }

        // ---- exp + row-sum partials + write E hi/lo into SMEM ----
        {
            float rsum[2][2] = {{0.f, 0.f}, {0.f, 0.f}};
#pragma unroll
            for (int i = 0; i < 2; i++) {
                const int rA = m0w + i * 16 + r4;
#pragma unroll
                for (int j = 0; j < 8; j++) {
                    const int col = n0w + j * 8 + c2;
                    float e0 = __expf(eacc[i][j][0]), e1 = __expf(eacc[i][j][1]);
                    float e2 = __expf(eacc[i][j][2]), e3 = __expf(eacc[i][j][3]);
                    rsum[i][0] += e0 + e1; rsum[i][1] += e2 + e3;
                    __nv_bfloat16 h, l; ushort2 ph, pl;
                    split2(e0, h, l); ph.x = __bfloat16_as_ushort(h); pl.x = __bfloat16_as_ushort(l);
                    split2(e1, h, l); ph.y = __bfloat16_as_ushort(h); pl.y = __bfloat16_as_ushort(l);
                    *(ushort2*)&sEh[rA * PX + col] = ph;
                    *(ushort2*)&sEl[rA * PX + col] = pl;
                    split2(e2, h, l); ph.x = __bfloat16_as_ushort(h); pl.x = __bfloat16_as_ushort(l);
                    split2(e3, h, l); ph.y = __bfloat16_as_ushort(h); pl.y = __bfloat16_as_ushort(l);
                    *(ushort2*)&sEh[(rA + 8) * PX + col] = ph;
                    *(ushort2*)&sEl[(rA + 8) * PX + col] = pl;
                }
            }
#pragma unroll
            for (int i = 0; i < 2; i++)
#pragma unroll
                for (int hh = 0; hh < 2; hh++) {
                    float s = rsum[i][hh];
                    s += __shfl_xor_sync(0xFFFFFFFF, s, 1);
                    s += __shfl_xor_sync(0xFFFFFFFF, s, 2);
                    rsum[i][hh] = s;
                }
            if ((L & 3) == 0) {
                const int nt = ch * 4 + sub;
                float* sp = g_sumP + (((size_t)b * 128 + nt) * 2 + wn) * CD;
                sp[m0w + r4]      = rsum[0][0];
                sp[m0w + r4 + 8]  = rsum[0][1];
                sp[m0w + r4 + 16] = rsum[1][0];
                sp[m0w + r4 + 24] = rsum[1][1];
            }
        }
        __syncthreads();   // E tile visible to all warps

        // ---- S-GEMM: sacc += E (rows d, K = n) x X (rows c, K = n) ----
#pragma unroll
        for (int kk = 0; kk < 128; kk += 16) {
            uint32_t ah[2][4], al[2][4];
#pragma unroll
            for (int i = 0; i < 2; i++) {
                uint32_t off = (uint32_t)(((m0w + i * 16 + (L & 15)) * PX
                                + kk + ((L >> 4) << 3)) * 2);
                LDSM4(ah[i][0], ah[i][1], ah[i][2], ah[i][3], uEh + off);
                LDSM4(al[i][0], al[i][1], al[i][2], al[i][3], uEl + off);
            }
#pragma unroll
            for (int j2 = 0; j2 < 4; j2++) {
                uint32_t h0, h1, h2, h3, l0, l1, l2, l3;
                uint32_t off = (uint32_t)(((n0w + j2 * 16 + (L & 15)) * PX
                                + kk + ((L >> 4) << 3)) * 2);
                LDSM4(h0, h2, h1, h3, uXh + off);   // j uses (r0,r2) and (r1,r3)
                LDSM4(l0, l2, l1, l3, uXl + off);
#pragma unroll
                for (int i = 0; i < 2; i++) {
                    MMA16816(sacc[i][2 * j2],     ah[i], h0, h1);
                    MMA16816(sacc[i][2 * j2],     ah[i], l0, l1);
                    MMA16816(sacc[i][2 * j2],     al[i], h0, h1);
                    MMA16816(sacc[i][2 * j2 + 1], ah[i], h2, h3);
                    MMA16816(sacc[i][2 * j2 + 1], ah[i], l2, l3);
                    MMA16816(sacc[i][2 * j2 + 1], al[i], h2, h3);
                }
            }
        }
        __syncthreads();   // done reading sX/sE before next subtile overwrites
    }

    // ---- write Spart ----
    float* sp = g_Spart + ((size_t)(b * NCH + ch)) * CD * CD;
#pragma unroll
    for (int i = 0; i < 2; i++) {
        const int rA = m0w + i * 16 + r4;
#pragma unroll
        for (int j = 0; j < 8; j++) {
            const int col = n0w + j * 8 + c2;
            *(float2*)(sp + rA * CD + col)       = make_float2(sacc[i][j][0], sacc[i][j][1]);
            *(float2*)(sp + (rA + 8) * CD + col) = make_float2(sacc[i][j][2], sacc[i][j][3]);
        }
    }
}

// ---------------------------------------------------------------------------
// gemm_out: y = M_b X + b_out  (identical to R9/R12 MODE2)
// ---------------------------------------------------------------------------
__global__ __launch_bounds__(256, 2) void gemm_out(
    const float* __restrict__ X, const float* __restrict__ bias,
    float* __restrict__ Y)
{
    __shared__ __nv_bfloat16 sAh[128 * PA], sAl[128 * PA];
    __shared__ __nv_bfloat16 sBh[32 * PB],  sBl[32 * PB];

    const int t = threadIdx.x, wid = t >> 5, L = t & 31;
    const int b = blockIdx.y, nt = blockIdx.x;
    const int n0 = nt * 128;
    const int wm = wid & 3, wn = wid >> 2;
    const int m0w = wm * 32, n0w = wn * 64;

    float acc[2][8][4];
#pragma unroll
    for (int i = 0; i < 2; i++)
#pragma unroll
        for (int j = 0; j < 8; j++)
#pragma unroll
            for (int q = 0; q < 4; q++) acc[i][j][q] = 0.f;

    const uint32_t uAh = sm_u32(sAh), uAl = sm_u32(sAl);
    const uint32_t uBh = sm_u32(sBh), uBl = sm_u32(sBl);

    for (int st = 0; st < 4; st++) {
        {
            const float* A = g_M + (size_t)b * CD * CD;
            const int k0 = st * 32;
            const int row = t >> 1, cbase = (t & 1) * 16;
#pragma unroll
            for (int i = 0; i < 4; i++) {
                int col = cbase + i * 4;
                float4 v = *(const float4*)(A + row * CD + k0 + col);
                ull vh, vl; split4(v, vh, vl);
                *(ull*)&sAh[row * PA + col] = vh;
                *(ull*)&sAl[row * PA + col] = vl;
            }
        }
        {
            const int k0 = st * 32;
            const float* B = X + ((size_t)b * CD + k0) * NND + n0;
            const int row = t >> 3, cb = (t & 7) * 16;
#pragma unroll
            for (int i = 0; i < 4; i++) {
                int col = cb + i * 4;
                float4 v = *(const float4*)(B + (size_t)row * NND + col);
                ull vh, vl; split4(v, vh, vl);
                *(ull*)&sBh[row * PB + col] = vh;
                *(ull*)&sBl[row * PB + col] = vl;
            }
        }
        __syncthreads();

#pragma unroll
        for (int kk = 0; kk < 32; kk += 16) {
            uint32_t ah[2][4], al[2][4];
#pragma unroll
            for (int i = 0; i < 2; i++) {
                uint32_t off = (uint32_t)(((m0w + i * 16 + (L & 15)) * PA
                                + kk + ((L >> 4) << 3)) * 2);
                LDSM4(ah[i][0], ah[i][1], ah[i][2], ah[i][3], uAh + off);
                LDSM4(al[i][0], al[i][1], al[i][2], al[i][3], uAl + off);
            }
#pragma unroll
            for (int j2 = 0; j2 < 4; j2++) {
                uint32_t h0, h1, h2, h3, l0, l1, l2, l3;
                uint32_t off = (uint32_t)(((kk + (L & 15)) * PB
                                + n0w + j2 * 16 + ((L >> 4) << 3)) * 2);
                LDSM4T(h0, h1, h2, h3, uBh + off);
                LDSM4T(l0, l1, l2, l3, uBl + off);
#pragma unroll
                for (int i = 0; i < 2; i++) {
                    MMA16816(acc[i][2 * j2],     ah[i], h0, h1);
                    MMA16816(acc[i][2 * j2],     ah[i], l0, l1);
                    MMA16816(acc[i][2 * j2],     al[i], h0, h1);
                    MMA16816(acc[i][2 * j2 + 1], ah[i], h2, h3);
                    MMA16816(acc[i][2 * j2 + 1], ah[i], l2, l3);
                    MMA16816(acc[i][2 * j2 + 1], al[i], h2, h3);
                }
            }
        }
        __syncthreads();
    }

    const int r4 = L >> 2, c2 = (L & 3) * 2;
#pragma unroll
    for (int i = 0; i < 2; i++) {
        const int rA = m0w + i * 16 + r4;
        const float b1 = bias[rA], b2 = bias[rA + 8];
#pragma unroll
        for (int j = 0; j < 8; j++) {
            const int col = n0 + n0w + j * 8 + c2;
            *(float2*)(Y + ((size_t)(b * CD + rA)) * NND + col) =
                make_float2(acc[i][j][0] + b1, acc[i][j][1] + b1);
            *(float2*)(Y + ((size_t)(b * CD + rA + 8)) * NND + col) =
                make_float2(acc[i][j][2] + b2, acc[i][j][3] + b2);
        }
    }
}

// ---------------------------------------------------------------------------
__global__ void reduce_scale()
{
    const int bd = blockIdx.x;
    const int c  = threadIdx.x;
    const int b  = bd >> 7, d = bd & 127;

    __shared__ float red[128];
    const float* sp = g_sumP + (size_t)b * 128 * 2 * CD;
    red[c] = sp[(c * 2 + 0) * CD + d] + sp[(c * 2 + 1) * CD + d];
    __syncthreads();
    for (int off = 64; off > 0; off >>= 1) {
        if (c < off) red[c] += red[c + off];
        __syncthreads();
    }
    const float inv = 1.0f / red[0];

    float s = 0.f;
    const float* p = g_Spart + (size_t)(b * NCH) * CD * CD + (size_t)d * CD + c;
    for (int ch = 0; ch < NCH; ch++) s += p[(size_t)ch * CD * CD];
    g_S[(size_t)bd * CD + c] = s * inv;
}

__global__ __launch_bounds__(1024) void ctx_kernel(const float* __restrict__ w_qkv)
{
    const int b = blockIdx.x, h = blockIdx.y;
    __shared__ float sS[32][133];
    __shared__ float sV[32][133];
    const int t = threadIdx.x;
#pragma unroll
    for (int p = 0; p < 4; p++) {
        int idx = p * 1024 + t;
        int dd = idx >> 7, c = idx & 127;
        sS[dd][c] = g_S[(size_t)(b * CD + h * 32 + dd) * CD + c];
        sV[dd][c] = w_qkv[(256 + h * 32 + dd) * CD + c];
    }
    __syncthreads();
    const int d = t >> 5, e = t & 31;
    float a = 0.f;
#pragma unroll 4
    for (int c = 0; c < CD; c++) a += sS[d][c] * sV[e][c];
    g_ctx[(size_t)(b * 4 + h) * 1024 + d * 32 + e] = a;
}

__global__ __launch_bounds__(1024) void u_kernel(const float* __restrict__ w_out)
{
    const int b = blockIdx.x;
    __shared__ float sc[128 * 33];
    const int t = threadIdx.x;
#pragma unroll
    for (int p = 0; p < 4; p++) {
        int idx = p * 1024 + t;
        sc[(idx >> 5) * 33 + (idx & 31)] = g_ctx[(size_t)b * 4096 + idx];
    }
    __syncthreads();
#pragma unroll
    for (int i = 0; i < 16; i++) {
        int m = i * 1024 + t;
        int o = m >> 7, hd = m & 127;
        const float* wrow = w_out + o * CD + (hd & ~31);
        const float* crow = sc + hd * 33;
        float a = 0.f;
#pragma unroll
        for (int e = 0; e < 32; e++) a += __ldg(wrow + e) * crow[e];
        g_U[(size_t)b * CD * CD + m] = a;
    }
}

__global__ __launch_bounds__(256) void m_kernel(const float* __restrict__ w_qkv)
{
    const int b = blockIdx.x, ct = blockIdx.y;
    __shared__ float sU[128 * 33];
    __shared__ float sQ[32 * 33];
    const int t  = threadIdx.x;
    const int cl = t & 31, og = t >> 5;

    float a[16];
#pragma unroll
    for (int i = 0; i < 16; i++) a[i] = 0.f;

    for (int kc = 0; kc < 4; kc++) {
        int k0 = kc * 32;
        __syncthreads();
#pragma unroll
        for (int p = 0; p < 16; p++) {
            int idx = p * 256 + t;
            sU[(idx >> 5) * 33 + (idx & 31)] =
                g_U[(size_t)b * CD * CD + (idx >> 5) * CD + k0 + (idx & 31)];
        }
#pragma unroll
        for (int p = 0; p < 4; p++) {
            int idx = p * 256 + t;
            sQ[(idx >> 5) * 33 + (idx & 31)] =
                w_qkv[(k0 + (idx >> 5)) * CD + ct * 32 + (idx & 31)];
        }
        __syncthreads();
#pragma unroll 8
        for (int kk = 0; kk < 32; kk++) {
            float bv = sQ[kk * 33 + cl];
#pragma unroll
            for (int i = 0; i < 16; i++) a[i] += sU[(og * 16 + i) * 33 + kk] * bv;
        }
    }
#pragma unroll
    for (int i = 0; i < 16; i++)
        g_M[(size_t)b * CD * CD + (og * 16 + i) * CD + ct * 32 + cl] = a[i];
}

// ---------------------------------------------------------------------------
// kernel_launch: stateless; unconditional idempotent attribute call + launches.
// ---------------------------------------------------------------------------
extern "C" void kernel_launch(void* const* d_in, const int* in_sizes, int n_in,
                              void* d_out, int out_size)
{
    const float* x     = (const float*)d_in[0];
    const float* w_qkv = (const float*)d_in[1];
    const float* w_out = (const float*)d_in[2];
    const float* b_out = (const float*)d_in[3];
    float* y = (float*)d_out;

    cudaFuncSetAttribute(fused_es, cudaFuncAttributeMaxDynamicSharedMemorySize, SMEM_FUSED);

    fused_es<<<dim3(NCH, BATCH), 256, SMEM_FUSED>>>(w_qkv + 128 * CD, x);
    reduce_scale<<<1024, 128>>>();
    ctx_kernel<<<dim3(BATCH, 4), 1024>>>(w_qkv);
    u_kernel<<<BATCH, 1024>>>(w_out);
    m_kernel<<<dim3(BATCH, 4), 256>>>(w_qkv);
    gemm_out<<<dim3(128, BATCH), 256>>>(x, b_out, y);
}

// round 15
// speedup vs baseline: 1.3000x; 1.0634x over previous
#include <cuda_runtime.h>
#include <cuda_bf16.h>
#include <cstdint>

// LinearAttention via mma.sync bf16 (sm_100-safe target).
//   fused_es  : per (b, 512-col chunk): E = exp(W_k x) per 128-col subtile,
//               consumed IN SMEM by Spart += E X^T. E never touches GMEM.
//   reduce_scale : S = (sum_ch Spart) / rowsum   (4-way MLP unroll)
//   ctxu_kernel  : per (b,h): ctx = S_h Wv_h^T (smem) then U cols for head h
//                  (replaces ctx_kernel + u_kernel; same summation order)
//   m_kernel     : M = U W_q
//   gemm_out     : y = M_b x + b_out
// 3-way bf16 split (hh+hl+lh) in fp32 accum; rel_err must stay 5.607987e-06.

#define BATCH 8
#define CD    128
#define NND   16384
#define NCH   32

typedef unsigned long long ull;

__device__ float g_sumP [BATCH * 128 * 2 * CD];
__device__ float g_Spart[BATCH * NCH * CD * CD];
__device__ float g_S    [BATCH * CD * CD];
__device__ float g_U    [BATCH * CD * CD];
__device__ float g_M    [BATCH * CD * CD];

__device__ __forceinline__ uint32_t sm_u32(const void* p) {
    uint32_t a;
    asm("{ .reg .u64 t; cvta.to.shared.u64 t, %1; cvt.u32.u64 %0, t; }" : "=r"(a) : "l"(p));
    return a;
}

#define LDSM4(r0, r1, r2, r3, a) \
    asm volatile("ldmatrix.sync.aligned.m8n8.x4.shared.b16 {%0,%1,%2,%3}, [%4];" \
                 : "=r"(r0), "=r"(r1), "=r"(r2), "=r"(r3) : "r"(a))
#define LDSM4T(r0, r1, r2, r3, a) \
    asm volatile("ldmatrix.sync.aligned.m8n8.x4.trans.shared.b16 {%0,%1,%2,%3}, [%4];" \
                 : "=r"(r0), "=r"(r1), "=r"(r2), "=r"(r3) : "r"(a))
#define MMA16816(d, av, b0, b1) \
    asm volatile("mma.sync.aligned.m16n8k16.row.col.f32.bf16.bf16.f32 " \
                 "{%0,%1,%2,%3}, {%4,%5,%6,%7}, {%8,%9}, {%0,%1,%2,%3};" \
                 : "+f"((d)[0]), "+f"((d)[1]), "+f"((d)[2]), "+f"((d)[3]) \
                 : "r"((av)[0]), "r"((av)[1]), "r"((av)[2]), "r"((av)[3]), \
                   "r"(b0), "r"(b1))

__device__ __forceinline__ void split2(float f, __nv_bfloat16& h, __nv_bfloat16& l) {
    h = __float2bfloat16(f);
    l = __float2bfloat16(f - __bfloat162float(h));
}
__device__ __forceinline__ void split4(float4 v, ull& vh, ull& vl) {
    float f[4] = {v.x, v.y, v.z, v.w};
    vh = 0; vl = 0;
#pragma unroll
    for (int j = 0; j < 4; j++) {
        __nv_bfloat16 h, l; split2(f[j], h, l);
        vh |= (ull)__bfloat16_as_ushort(h) << (16 * j);
        vl |= (ull)__bfloat16_as_ushort(l) << (16 * j);
    }
}

// pitches (bf16 elems)
#define PX 136    // fused kernel tiles; 272B rows, conflict-free both ldmatrix modes
#define PA 40     // gemm_out A tiles
#define PB 136    // gemm_out trans-B tiles

#define TSZ       (128 * PX)
#define SMEM_FUSED (6 * TSZ * 2)      // 208896 B

// ---------------------------------------------------------------------------
// fused_es: one CTA per (chunk, batch). 256 threads, 8 warps (4m x 2n).
// ---------------------------------------------------------------------------
__global__ __launch_bounds__(256) void fused_es(
    const float* __restrict__ Wk, const float* __restrict__ X)
{
    extern __shared__ __nv_bfloat16 sm[];
    __nv_bfloat16* sWh = sm;
    __nv_bfloat16* sWl = sm + TSZ;
    __nv_bfloat16* sXh = sm + 2 * TSZ;
    __nv_bfloat16* sXl = sm + 3 * TSZ;
    __nv_bfloat16* sEh = sm + 4 * TSZ;
    __nv_bfloat16* sEl = sm + 5 * TSZ;

    const int t = threadIdx.x, wid = t >> 5, L = t & 31;
    const int ch = blockIdx.x, b = blockIdx.y;
    const int wm = wid & 3, wn = wid >> 2;
    const int m0w = wm * 32, n0w = wn * 64;
    const int r4 = L >> 2, c2 = (L & 3) * 2;

    const uint32_t uWh = sm_u32(sWh), uWl = sm_u32(sWl);
    const uint32_t uXh = sm_u32(sXh), uXl = sm_u32(sXl);
    const uint32_t uEh = sm_u32(sEh), uEl = sm_u32(sEl);

    // ---- stage W once ----
    {
        const int row = t >> 1, cb = (t & 1) * 64;
#pragma unroll
        for (int i = 0; i < 16; i++) {
            int col = cb + i * 4;
            float4 v = *(const float4*)(Wk + row * CD + col);
            ull vh, vl; split4(v, vh, vl);
            *(ull*)&sWh[row * PX + col] = vh;
            *(ull*)&sWl[row * PX + col] = vl;
        }
    }

    float sacc[2][8][4];
#pragma unroll
    for (int i = 0; i < 2; i++)
#pragma unroll
        for (int j = 0; j < 8; j++)
#pragma unroll
            for (int q = 0; q < 4; q++) sacc[i][j][q] = 0.f;

    for (int sub = 0; sub < 4; sub++) {
        const int n0 = ch * 512 + sub * 128;

        // ---- stage X subtile ----
        {
            const int row = t >> 1, cb = (t & 1) * 64;
#pragma unroll
            for (int i = 0; i < 16; i++) {
                int col = cb + i * 4;
                float4 v = *(const float4*)(X + ((size_t)(b * CD) + row) * NND + n0 + col);
                ull vh, vl; split4(v, vh, vl);
                *(ull*)&sXh[row * PX + col] = vh;
                *(ull*)&sXl[row * PX + col] = vl;
            }
        }
        __syncthreads();

        // ---- E-GEMM ----
        float eacc[2][8][4];
#pragma unroll
        for (int i = 0; i < 2; i++)
#pragma unroll
            for (int j = 0; j < 8; j++)
#pragma unroll
                for (int q = 0; q < 4; q++) eacc[i][j][q] = 0.f;

#pragma unroll
        for (int kk = 0; kk < 128; kk += 16) {
            uint32_t ah[2][4], al[2][4];
#pragma unroll
            for (int i = 0; i < 2; i++) {
                uint32_t off = (uint32_t)(((m0w + i * 16 + (L & 15)) * PX
                                + kk + ((L >> 4) << 3)) * 2);
                LDSM4(ah[i][0], ah[i][1], ah[i][2], ah[i][3], uWh + off);
                LDSM4(al[i][0], al[i][1], al[i][2], al[i][3], uWl + off);
            }
#pragma unroll
            for (int j2 = 0; j2 < 4; j2++) {
                uint32_t h0, h1, h2, h3, l0, l1, l2, l3;
                uint32_t off = (uint32_t)(((kk + (L & 15)) * PX
                                + n0w + j2 * 16 + ((L >> 4) << 3)) * 2);
                LDSM4T(h0, h1, h2, h3, uXh + off);
                LDSM4T(l0, l1, l2, l3, uXl + off);
#pragma unroll
                for (int i = 0; i < 2; i++) {
                    MMA16816(eacc[i][2 * j2],     ah[i], h0, h1);
                    MMA16816(eacc[i][2 * j2],     ah[i], l0, l1);
                    MMA16816(eacc[i][2 * j2],     al[i], h0, h1);
                    MMA16816(eacc[i][2 * j2 + 1], ah[i], h2, h3);
                    MMA16816(eacc[i][2 * j2 + 1], ah[i], l2, l3);
                    MMA16816(eacc[i][2 * j2 + 1], al[i], h2, h3);
                }
            }
        }

        // ---- exp + row-sum partials + E -> SMEM ----
        {
            float rsum[2][2] = {{0.f, 0.f}, {0.f, 0.f}};
#pragma unroll
            for (int i = 0; i < 2; i++) {
                const int rA = m0w + i * 16 + r4;
#pragma unroll
                for (int j = 0; j < 8; j++) {
                    const int col = n0w + j * 8 + c2;
                    float e0 = __expf(eacc[i][j][0]), e1 = __expf(eacc[i][j][1]);
                    float e2 = __expf(eacc[i][j][2]), e3 = __expf(eacc[i][j][3]);
                    rsum[i][0] += e0 + e1; rsum[i][1] += e2 + e3;
                    __nv_bfloat16 h, l; ushort2 ph, pl;
                    split2(e0, h, l); ph.x = __bfloat16_as_ushort(h); pl.x = __bfloat16_as_ushort(l);
                    split2(e1, h, l); ph.y = __bfloat16_as_ushort(h); pl.y = __bfloat16_as_ushort(l);
                    *(ushort2*)&sEh[rA * PX + col] = ph;
                    *(ushort2*)&sEl[rA * PX + col] = pl;
                    split2(e2, h, l); ph.x = __bfloat16_as_ushort(h); pl.x = __bfloat16_as_ushort(l);
                    split2(e3, h, l); ph.y = __bfloat16_as_ushort(h); pl.y = __bfloat16_as_ushort(l);
                    *(ushort2*)&sEh[(rA + 8) * PX + col] = ph;
                    *(ushort2*)&sEl[(rA + 8) * PX + col] = pl;
                }
            }
#pragma unroll
            for (int i = 0; i < 2; i++)
#pragma unroll
                for (int hh = 0; hh < 2; hh++) {
                    float s = rsum[i][hh];
                    s += __shfl_xor_sync(0xFFFFFFFF, s, 1);
                    s += __shfl_xor_sync(0xFFFFFFFF, s, 2);
                    rsum[i][hh] = s;
                }
            if ((L & 3) == 0) {
                const int nt = ch * 4 + sub;
                float* sp = g_sumP + (((size_t)b * 128 + nt) * 2 + wn) * CD;
                sp[m0w + r4]      = rsum[0][0];
                sp[m0w + r4 + 8]  = rsum[0][1];
                sp[m0w + r4 + 16] = rsum[1][0];
                sp[m0w + r4 + 24] = rsum[1][1];
            }
        }
        __syncthreads();

        // ---- S-GEMM ----
#pragma unroll
        for (int kk = 0; kk < 128; kk += 16) {
            uint32_t ah[2][4], al[2][4];
#pragma unroll
            for (int i = 0; i < 2; i++) {
                uint32_t off = (uint32_t)(((m0w + i * 16 + (L & 15)) * PX
                                + kk + ((L >> 4) << 3)) * 2);
                LDSM4(ah[i][0], ah[i][1], ah[i][2], ah[i][3], uEh + off);
                LDSM4(al[i][0], al[i][1], al[i][2], al[i][3], uEl + off);
            }
#pragma unroll
            for (int j2 = 0; j2 < 4; j2++) {
                uint32_t h0, h1, h2, h3, l0, l1, l2, l3;
                uint32_t off = (uint32_t)(((n0w + j2 * 16 + (L & 15)) * PX
                                + kk + ((L >> 4) << 3)) * 2);
                LDSM4(h0, h2, h1, h3, uXh + off);
                LDSM4(l0, l2, l1, l3, uXl + off);
#pragma unroll
                for (int i = 0; i < 2; i++) {
                    MMA16816(sacc[i][2 * j2],     ah[i], h0, h1);
                    MMA16816(sacc[i][2 * j2],     ah[i], l0, l1);
                    MMA16816(sacc[i][2 * j2],     al[i], h0, h1);
                    MMA16816(sacc[i][2 * j2 + 1], ah[i], h2, h3);
                    MMA16816(sacc[i][2 * j2 + 1], ah[i], l2, l3);
                    MMA16816(sacc[i][2 * j2 + 1], al[i], h2, h3);
                }
            }
        }
        __syncthreads();
    }

    // ---- write Spart ----
    float* sp = g_Spart + ((size_t)(b * NCH + ch)) * CD * CD;
#pragma unroll
    for (int i = 0; i < 2; i++) {
        const int rA = m0w + i * 16 + r4;
#pragma unroll
        for (int j = 0; j < 8; j++) {
            const int col = n0w + j * 8 + c2;
            *(float2*)(sp + rA * CD + col)       = make_float2(sacc[i][j][0], sacc[i][j][1]);
            *(float2*)(sp + (rA + 8) * CD + col) = make_float2(sacc[i][j][2], sacc[i][j][3]);
        }
    }
}

// ---------------------------------------------------------------------------
// gemm_out: y = M_b X + b_out
// ---------------------------------------------------------------------------
__global__ __launch_bounds__(256, 2) void gemm_out(
    const float* __restrict__ X, const float* __restrict__ bias,
    float* __restrict__ Y)
{
    __shared__ __nv_bfloat16 sAh[128 * PA], sAl[128 * PA];
    __shared__ __nv_bfloat16 sBh[32 * PB],  sBl[32 * PB];

    const int t = threadIdx.x, wid = t >> 5, L = t & 31;
    const int b = blockIdx.y, nt = blockIdx.x;
    const int n0 = nt * 128;
    const int wm = wid & 3, wn = wid >> 2;
    const int m0w = wm * 32, n0w = wn * 64;

    float acc[2][8][4];
#pragma unroll
    for (int i = 0; i < 2; i++)
#pragma unroll
        for (int j = 0; j < 8; j++)
#pragma unroll
            for (int q = 0; q < 4; q++) acc[i][j][q] = 0.f;

    const uint32_t uAh = sm_u32(sAh), uAl = sm_u32(sAl);
    const uint32_t uBh = sm_u32(sBh), uBl = sm_u32(sBl);

    for (int st = 0; st < 4; st++) {
        {
            const float* A = g_M + (size_t)b * CD * CD;
            const int k0 = st * 32;
            const int row = t >> 1, cbase = (t & 1) * 16;
#pragma unroll
            for (int i = 0; i < 4; i++) {
                int col = cbase + i * 4;
                float4 v = *(const float4*)(A + row * CD + k0 + col);
                ull vh, vl; split4(v, vh, vl);
                *(ull*)&sAh[row * PA + col] = vh;
                *(ull*)&sAl[row * PA + col] = vl;
            }
        }
        {
            const int k0 = st * 32;
            const float* B = X + ((size_t)b * CD + k0) * NND + n0;
            const int row = t >> 3, cb = (t & 7) * 16;
#pragma unroll
            for (int i = 0; i < 4; i++) {
                int col = cb + i * 4;
                float4 v = *(const float4*)(B + (size_t)row * NND + col);
                ull vh, vl; split4(v, vh, vl);
                *(ull*)&sBh[row * PB + col] = vh;
                *(ull*)&sBl[row * PB + col] = vl;
            }
        }
        __syncthreads();

#pragma unroll
        for (int kk = 0; kk < 32; kk += 16) {
            uint32_t ah[2][4], al[2][4];
#pragma unroll
            for (int i = 0; i < 2; i++) {
                uint32_t off = (uint32_t)(((m0w + i * 16 + (L & 15)) * PA
                                + kk + ((L >> 4) << 3)) * 2);
                LDSM4(ah[i][0], ah[i][1], ah[i][2], ah[i][3], uAh + off);
                LDSM4(al[i][0], al[i][1], al[i][2], al[i][3], uAl + off);
            }
#pragma unroll
            for (int j2 = 0; j2 < 4; j2++) {
                uint32_t h0, h1, h2, h3, l0, l1, l2, l3;
                uint32_t off = (uint32_t)(((kk + (L & 15)) * PB
                                + n0w + j2 * 16 + ((L >> 4) << 3)) * 2);
                LDSM4T(h0, h1, h2, h3, uBh + off);
                LDSM4T(l0, l1, l2, l3, uBl + off);
#pragma unroll
                for (int i = 0; i < 2; i++) {
                    MMA16816(acc[i][2 * j2],     ah[i], h0, h1);
                    MMA16816(acc[i][2 * j2],     ah[i], l0, l1);
                    MMA16816(acc[i][2 * j2],     al[i], h0, h1);
                    MMA16816(acc[i][2 * j2 + 1], ah[i], h2, h3);
                    MMA16816(acc[i][2 * j2 + 1], ah[i], l2, l3);
                    MMA16816(acc[i][2 * j2 + 1], al[i], h2, h3);
                }
            }
        }
        __syncthreads();
    }

    const int r4 = L >> 2, c2 = (L & 3) * 2;
#pragma unroll
    for (int i = 0; i < 2; i++) {
        const int rA = m0w + i * 16 + r4;
        const float b1 = bias[rA], b2 = bias[rA + 8];
#pragma unroll
        for (int j = 0; j < 8; j++) {
            const int col = n0 + n0w + j * 8 + c2;
            *(float2*)(Y + ((size_t)(b * CD + rA)) * NND + col) =
                make_float2(acc[i][j][0] + b1, acc[i][j][1] + b1);
            *(float2*)(Y + ((size_t)(b * CD + rA + 8)) * NND + col) =
                make_float2(acc[i][j][2] + b2, acc[i][j][3] + b2);
        }
    }
}

// ---------------------------------------------------------------------------
// reduce_scale: 4 independent partial sums over ch (MLP >= 4).
// ---------------------------------------------------------------------------
__global__ void reduce_scale()
{
    const int bd = blockIdx.x;
    const int c  = threadIdx.x;
    const int b  = bd >> 7, d = bd & 127;

    __shared__ float red[128];
    const float* sp = g_sumP + (size_t)b * 128 * 2 * CD;
    red[c] = sp[(c * 2 + 0) * CD + d] + sp[(c * 2 + 1) * CD + d];
    __syncthreads();
    for (int off = 64; off > 0; off >>= 1) {
        if (c < off) red[c] += red[c + off];
        __syncthreads();
    }
    const float inv = 1.0f / red[0];

    const float* p = g_Spart + (size_t)(b * NCH) * CD * CD + (size_t)d * CD + c;
    float s0 = 0.f, s1 = 0.f, s2 = 0.f, s3 = 0.f;
#pragma unroll
    for (int ch = 0; ch < NCH; ch += 4) {
        s0 += p[(size_t)(ch + 0) * CD * CD];
        s1 += p[(size_t)(ch + 1) * CD * CD];
        s2 += p[(size_t)(ch + 2) * CD * CD];
        s3 += p[(size_t)(ch + 3) * CD * CD];
    }
    g_S[(size_t)bd * CD + c] = ((s0 + s1) + (s2 + s3)) * inv;
}

// ---------------------------------------------------------------------------
// ctxu_kernel: per (b, h). Computes ctx (in smem) and head-h columns of U.
//   ctx[d_][e] = sum_c S[b][h*32+d_][c] * Wv[h*32+e][c]    (serial c, as before)
//   U[b][o][h*32+d_] = sum_e Wout[o][h*32+e] * ctx[d_][e]  (serial e, as before)
// ---------------------------------------------------------------------------
#define PS 133
__global__ __launch_bounds__(256) void ctxu_kernel(
    const float* __restrict__ w_qkv, const float* __restrict__ w_out)
{
    const int b = blockIdx.x, h = blockIdx.y;
    __shared__ float sS[32 * PS];      // reused as sWo[128][33] in stage 2
    __shared__ float sV[32 * PS];
    __shared__ float sCtx[32 * 33];
    const int t = threadIdx.x;

    // stage S slice + Wv slice (32 rows x 128 c each)
#pragma unroll
    for (int p = 0; p < 16; p++) {
        int idx = p * 256 + t;
        int row = idx >> 7, c = idx & 127;
        sS[row * PS + c] = g_S[(size_t)(b * CD + h * 32 + row) * CD + c];
        sV[row * PS + c] = w_qkv[(256 + h * 32 + row) * CD + c];
    }
    __syncthreads();

    // ctx: 1024 outputs, 4 per thread; serial c-sum (order matches old ctx_kernel)
#pragma unroll
    for (int p = 0; p < 4; p++) {
        int idx = p * 256 + t;
        int d_ = idx >> 5, e = idx & 31;
        float a = 0.f;
#pragma unroll 4
        for (int c = 0; c < CD; c++) a += sS[d_ * PS + c] * sV[e * PS + c];
        sCtx[d_ * 33 + e] = a;
    }
    __syncthreads();

    // overwrite sS with W_out[:, h*32 .. h*32+31]  (128 x 32, pitch 33)
    float* sWo = sS;
#pragma unroll
    for (int p = 0; p < 16; p++) {
        int idx = p * 256 + t;
        int o = idx >> 5, e = idx & 31;
        sWo[o * 33 + e] = w_out[o * CD + h * 32 + e];
    }
    __syncthreads();

    // U: 4096 outputs, 16 per thread; serial e-sum (order matches old u_kernel)
    const int og = t >> 5, d_ = t & 31;
#pragma unroll
    for (int p = 0; p < 16; p++) {
        int o = p * 8 + og;
        float a = 0.f;
#pragma unroll
        for (int e = 0; e < 32; e++) a += sWo[o * 33 + e] * sCtx[d_ * 33 + e];
        g_U[(size_t)b * CD * CD + o * CD + h * 32 + d_] = a;
    }
}

__global__ __launch_bounds__(256) void m_kernel(const float* __restrict__ w_qkv)
{
    const int b = blockIdx.x, ct = blockIdx.y;
    __shared__ float sU[128 * 33];
    __shared__ float sQ[32 * 33];
    const int t  = threadIdx.x;
    const int cl = t & 31, og = t >> 5;

    float a[16];
#pragma unroll
    for (int i = 0; i < 16; i++) a[i] = 0.f;

    for (int kc = 0; kc < 4; kc++) {
        int k0 = kc * 32;
        __syncthreads();
#pragma unroll
        for (int p = 0; p < 16; p++) {
            int idx = p * 256 + t;
            sU[(idx >> 5) * 33 + (idx & 31)] =
                g_U[(size_t)b * CD * CD + (idx >> 5) * CD + k0 + (idx & 31)];
        }
#pragma unroll
        for (int p = 0; p < 4; p++) {
            int idx = p * 256 + t;
            sQ[(idx >> 5) * 33 + (idx & 31)] =
                w_qkv[(k0 + (idx >> 5)) * CD + ct * 32 + (idx & 31)];
        }
        __syncthreads();
#pragma unroll 8
        for (int kk = 0; kk < 32; kk++) {
            float bv = sQ[kk * 33 + cl];
#pragma unroll
            for (int i = 0; i < 16; i++) a[i] += sU[(og * 16 + i) * 33 + kk] * bv;
        }
    }
#pragma unroll
    for (int i = 0; i < 16; i++)
        g_M[(size_t)b * CD * CD + (og * 16 + i) * CD + ct * 32 + cl] = a[i];
}

// ---------------------------------------------------------------------------
// kernel_launch: stateless; unconditional idempotent attribute call + launches.
// ---------------------------------------------------------------------------
extern "C" void kernel_launch(void* const* d_in, const int* in_sizes, int n_in,
                              void* d_out, int out_size)
{
    const float* x     = (const float*)d_in[0];
    const float* w_qkv = (const float*)d_in[1];
    const float* w_out = (const float*)d_in[2];
    const float* b_out = (const float*)d_in[3];
    float* y = (float*)d_out;

    cudaFuncSetAttribute(fused_es, cudaFuncAttributeMaxDynamicSharedMemorySize, SMEM_FUSED);

    fused_es<<<dim3(NCH, BATCH), 256, SMEM_FUSED>>>(w_qkv + 128 * CD, x);
    reduce_scale<<<1024, 128>>>();
    ctxu_kernel<<<dim3(BATCH, 4), 256>>>(w_qkv, w_out);
    m_kernel<<<dim3(BATCH, 4), 256>>>(w_qkv);
    gemm_out<<<dim3(128, BATCH), 256>>>(x, b_out, y);
}

// round 16
// speedup vs baseline: 1.3351x; 1.0270x over previous
#include <cuda_runtime.h>
#include <cuda_bf16.h>
#include <cstdint>

// LinearAttention via mma.sync bf16 (sm_100-safe target).
//   fused_es  : per (b, 512-col chunk): E = exp(W_k x) per 128-col subtile,
//               consumed IN SMEM by Spart += E X^T. E never touches GMEM.
//   reduce_scale : S = (sum_ch Spart) / rowsum   (4-way MLP unroll)
//   ctxu_kernel  : per (b,h): ctx = S_h Wv_h^T (smem) then U cols for head h
//   m_kernel     : M = U W_q   (grid 8x4x4 = 128 blocks; serial k order kept)
//   gemm_out     : y = M_b x + b_out
// 3-way bf16 split (hh+hl+lh) in fp32 accum; rel_err must stay 5.606697e-06.

#define BATCH 8
#define CD    128
#define NND   16384
#define NCH   32

typedef unsigned long long ull;

__device__ float g_sumP [BATCH * 128 * 2 * CD];
__device__ float g_Spart[BATCH * NCH * CD * CD];
__device__ float g_S    [BATCH * CD * CD];
__device__ float g_U    [BATCH * CD * CD];
__device__ float g_M    [BATCH * CD * CD];

__device__ __forceinline__ uint32_t sm_u32(const void* p) {
    uint32_t a;
    asm("{ .reg .u64 t; cvta.to.shared.u64 t, %1; cvt.u32.u64 %0, t; }" : "=r"(a) : "l"(p));
    return a;
}

#define LDSM4(r0, r1, r2, r3, a) \
    asm volatile("ldmatrix.sync.aligned.m8n8.x4.shared.b16 {%0,%1,%2,%3}, [%4];" \
                 : "=r"(r0), "=r"(r1), "=r"(r2), "=r"(r3) : "r"(a))
#define LDSM4T(r0, r1, r2, r3, a) \
    asm volatile("ldmatrix.sync.aligned.m8n8.x4.trans.shared.b16 {%0,%1,%2,%3}, [%4];" \
                 : "=r"(r0), "=r"(r1), "=r"(r2), "=r"(r3) : "r"(a))
#define MMA16816(d, av, b0, b1) \
    asm volatile("mma.sync.aligned.m16n8k16.row.col.f32.bf16.bf16.f32 " \
                 "{%0,%1,%2,%3}, {%4,%5,%6,%7}, {%8,%9}, {%0,%1,%2,%3};" \
                 : "+f"((d)[0]), "+f"((d)[1]), "+f"((d)[2]), "+f"((d)[3]) \
                 : "r"((av)[0]), "r"((av)[1]), "r"((av)[2]), "r"((av)[3]), \
                   "r"(b0), "r"(b1))

__device__ __forceinline__ void split2(float f, __nv_bfloat16& h, __nv_bfloat16& l) {
    h = __float2bfloat16(f);
    l = __float2bfloat16(f - __bfloat162float(h));
}
__device__ __forceinline__ void split4(float4 v, ull& vh, ull& vl) {
    float f[4] = {v.x, v.y, v.z, v.w};
    vh = 0; vl = 0;
#pragma unroll
    for (int j = 0; j < 4; j++) {
        __nv_bfloat16 h, l; split2(f[j], h, l);
        vh |= (ull)__bfloat16_as_ushort(h) << (16 * j);
        vl |= (ull)__bfloat16_as_ushort(l) << (16 * j);
    }
}

// pitches (bf16 elems)
#define PX 136
#define PA 40
#define PB 136

#define TSZ       (128 * PX)
#define SMEM_FUSED (6 * TSZ * 2)      // 208896 B

// ---------------------------------------------------------------------------
// fused_es: one CTA per (chunk, batch). 256 threads, 8 warps (4m x 2n).
// ---------------------------------------------------------------------------
__global__ __launch_bounds__(256) void fused_es(
    const float* __restrict__ Wk, const float* __restrict__ X)
{
    extern __shared__ __nv_bfloat16 sm[];
    __nv_bfloat16* sWh = sm;
    __nv_bfloat16* sWl = sm + TSZ;
    __nv_bfloat16* sXh = sm + 2 * TSZ;
    __nv_bfloat16* sXl = sm + 3 * TSZ;
    __nv_bfloat16* sEh = sm + 4 * TSZ;
    __nv_bfloat16* sEl = sm + 5 * TSZ;

    const int t = threadIdx.x, wid = t >> 5, L = t & 31;
    const int ch = blockIdx.x, b = blockIdx.y;
    const int wm = wid & 3, wn = wid >> 2;
    const int m0w = wm * 32, n0w = wn * 64;
    const int r4 = L >> 2, c2 = (L & 3) * 2;

    const uint32_t uWh = sm_u32(sWh), uWl = sm_u32(sWl);
    const uint32_t uXh = sm_u32(sXh), uXl = sm_u32(sXl);
    const uint32_t uEh = sm_u32(sEh), uEl = sm_u32(sEl);

    // ---- stage W once ----
    {
        const int row = t >> 1, cb = (t & 1) * 64;
#pragma unroll
        for (int i = 0; i < 16; i++) {
            int col = cb + i * 4;
            float4 v = *(const float4*)(Wk + row * CD + col);
            ull vh, vl; split4(v, vh, vl);
            *(ull*)&sWh[row * PX + col] = vh;
            *(ull*)&sWl[row * PX + col] = vl;
        }
    }

    float sacc[2][8][4];
#pragma unroll
    for (int i = 0; i < 2; i++)
#pragma unroll
        for (int j = 0; j < 8; j++)
#pragma unroll
            for (int q = 0; q < 4; q++) sacc[i][j][q] = 0.f;

    for (int sub = 0; sub < 4; sub++) {
        const int n0 = ch * 512 + sub * 128;

        // ---- stage X subtile ----
        {
            const int row = t >> 1, cb = (t & 1) * 64;
#pragma unroll
            for (int i = 0; i < 16; i++) {
                int col = cb + i * 4;
                float4 v = *(const float4*)(X + ((size_t)(b * CD) + row) * NND + n0 + col);
                ull vh, vl; split4(v, vh, vl);
                *(ull*)&sXh[row * PX + col] = vh;
                *(ull*)&sXl[row * PX + col] = vl;
            }
        }
        __syncthreads();

        // ---- E-GEMM ----
        float eacc[2][8][4];
#pragma unroll
        for (int i = 0; i < 2; i++)
#pragma unroll
            for (int j = 0; j < 8; j++)
#pragma unroll
                for (int q = 0; q < 4; q++) eacc[i][j][q] = 0.f;

#pragma unroll
        for (int kk = 0; kk < 128; kk += 16) {
            uint32_t ah[2][4], al[2][4];
#pragma unroll
            for (int i = 0; i < 2; i++) {
                uint32_t off = (uint32_t)(((m0w + i * 16 + (L & 15)) * PX
                                + kk + ((L >> 4) << 3)) * 2);
                LDSM4(ah[i][0], ah[i][1], ah[i][2], ah[i][3], uWh + off);
                LDSM4(al[i][0], al[i][1], al[i][2], al[i][3], uWl + off);
            }
#pragma unroll
            for (int j2 = 0; j2 < 4; j2++) {
                uint32_t h0, h1, h2, h3, l0, l1, l2, l3;
                uint32_t off = (uint32_t)(((kk + (L & 15)) * PX
                                + n0w + j2 * 16 + ((L >> 4) << 3)) * 2);
                LDSM4T(h0, h1, h2, h3, uXh + off);
                LDSM4T(l0, l1, l2, l3, uXl + off);
#pragma unroll
                for (int i = 0; i < 2; i++) {
                    MMA16816(eacc[i][2 * j2],     ah[i], h0, h1);
                    MMA16816(eacc[i][2 * j2],     ah[i], l0, l1);
                    MMA16816(eacc[i][2 * j2],     al[i], h0, h1);
                    MMA16816(eacc[i][2 * j2 + 1], ah[i], h2, h3);
                    MMA16816(eacc[i][2 * j2 + 1], ah[i], l2, l3);
                    MMA16816(eacc[i][2 * j2 + 1], al[i], h2, h3);
                }
            }
        }

        // ---- exp + row-sum partials + E -> SMEM ----
        {
            float rsum[2][2] = {{0.f, 0.f}, {0.f, 0.f}};
#pragma unroll
            for (int i = 0; i < 2; i++) {
                const int rA = m0w + i * 16 + r4;
#pragma unroll
                for (int j = 0; j < 8; j++) {
                    const int col = n0w + j * 8 + c2;
                    float e0 = __expf(eacc[i][j][0]), e1 = __expf(eacc[i][j][1]);
                    float e2 = __expf(eacc[i][j][2]), e3 = __expf(eacc[i][j][3]);
                    rsum[i][0] += e0 + e1; rsum[i][1] += e2 + e3;
                    __nv_bfloat16 h, l; ushort2 ph, pl;
                    split2(e0, h, l); ph.x = __bfloat16_as_ushort(h); pl.x = __bfloat16_as_ushort(l);
                    split2(e1, h, l); ph.y = __bfloat16_as_ushort(h); pl.y = __bfloat16_as_ushort(l);
                    *(ushort2*)&sEh[rA * PX + col] = ph;
                    *(ushort2*)&sEl[rA * PX + col] = pl;
                    split2(e2, h, l); ph.x = __bfloat16_as_ushort(h); pl.x = __bfloat16_as_ushort(l);
                    split2(e3, h, l); ph.y = __bfloat16_as_ushort(h); pl.y = __bfloat16_as_ushort(l);
                    *(ushort2*)&sEh[(rA + 8) * PX + col] = ph;
                    *(ushort2*)&sEl[(rA + 8) * PX + col] = pl;
                }
            }
#pragma unroll
            for (int i = 0; i < 2; i++)
#pragma unroll
                for (int hh = 0; hh < 2; hh++) {
                    float s = rsum[i][hh];
                    s += __shfl_xor_sync(0xFFFFFFFF, s, 1);
                    s += __shfl_xor_sync(0xFFFFFFFF, s, 2);
                    rsum[i][hh] = s;
                }
            if ((L & 3) == 0) {
                const int nt = ch * 4 + sub;
                float* sp = g_sumP + (((size_t)b * 128 + nt) * 2 + wn) * CD;
                sp[m0w + r4]      = rsum[0][0];
                sp[m0w + r4 + 8]  = rsum[0][1];
                sp[m0w + r4 + 16] = rsum[1][0];
                sp[m0w + r4 + 24] = rsum[1][1];
            }
        }
        __syncthreads();

        // ---- S-GEMM ----
#pragma unroll
        for (int kk = 0; kk < 128; kk += 16) {
            uint32_t ah[2][4], al[2][4];
#pragma unroll
            for (int i = 0; i < 2; i++) {
                uint32_t off = (uint32_t)(((m0w + i * 16 + (L & 15)) * PX
                                + kk + ((L >> 4) << 3)) * 2);
                LDSM4(ah[i][0], ah[i][1], ah[i][2], ah[i][3], uEh + off);
                LDSM4(al[i][0], al[i][1], al[i][2], al[i][3], uEl + off);
            }
#pragma unroll
            for (int j2 = 0; j2 < 4; j2++) {
                uint32_t h0, h1, h2, h3, l0, l1, l2, l3;
                uint32_t off = (uint32_t)(((n0w + j2 * 16 + (L & 15)) * PX
                                + kk + ((L >> 4) << 3)) * 2);
                LDSM4(h0, h2, h1, h3, uXh + off);
                LDSM4(l0, l2, l1, l3, uXl + off);
#pragma unroll
                for (int i = 0; i < 2; i++) {
                    MMA16816(sacc[i][2 * j2],     ah[i], h0, h1);
                    MMA16816(sacc[i][2 * j2],     ah[i], l0, l1);
                    MMA16816(sacc[i][2 * j2],     al[i], h0, h1);
                    MMA16816(sacc[i][2 * j2 + 1], ah[i], h2, h3);
                    MMA16816(sacc[i][2 * j2 + 1], ah[i], l2, l3);
                    MMA16816(sacc[i][2 * j2 + 1], al[i], h2, h3);
                }
            }
        }
        __syncthreads();
    }

    // ---- write Spart ----
    float* sp = g_Spart + ((size_t)(b * NCH + ch)) * CD * CD;
#pragma unroll
    for (int i = 0; i < 2; i++) {
        const int rA = m0w + i * 16 + r4;
#pragma unroll
        for (int j = 0; j < 8; j++) {
            const int col = n0w + j * 8 + c2;
            *(float2*)(sp + rA * CD + col)       = make_float2(sacc[i][j][0], sacc[i][j][1]);
            *(float2*)(sp + (rA + 8) * CD + col) = make_float2(sacc[i][j][2], sacc[i][j][3]);
        }
    }
}

// ---------------------------------------------------------------------------
// gemm_out: y = M_b X + b_out
// ---------------------------------------------------------------------------
__global__ __launch_bounds__(256, 2) void gemm_out(
    const float* __restrict__ X, const float* __restrict__ bias,
    float* __restrict__ Y)
{
    __shared__ __nv_bfloat16 sAh[128 * PA], sAl[128 * PA];
    __shared__ __nv_bfloat16 sBh[32 * PB],  sBl[32 * PB];

    const int t = threadIdx.x, wid = t >> 5, L = t & 31;
    const int b = blockIdx.y, nt = blockIdx.x;
    const int n0 = nt * 128;
    const int wm = wid & 3, wn = wid >> 2;
    const int m0w = wm * 32, n0w = wn * 64;

    float acc[2][8][4];
#pragma unroll
    for (int i = 0; i < 2; i++)
#pragma unroll
        for (int j = 0; j < 8; j++)
#pragma unroll
            for (int q = 0; q < 4; q++) acc[i][j][q] = 0.f;

    const uint32_t uAh = sm_u32(sAh), uAl = sm_u32(sAl);
    const uint32_t uBh = sm_u32(sBh), uBl = sm_u32(sBl);

    for (int st = 0; st < 4; st++) {
        {
            const float* A = g_M + (size_t)b * CD * CD;
            const int k0 = st * 32;
            const int row = t >> 1, cbase = (t & 1) * 16;
#pragma unroll
            for (int i = 0; i < 4; i++) {
                int col = cbase + i * 4;
                float4 v = *(const float4*)(A + row * CD + k0 + col);
                ull vh, vl; split4(v, vh, vl);
                *(ull*)&sAh[row * PA + col] = vh;
                *(ull*)&sAl[row * PA + col] = vl;
            }
        }
        {
            const int k0 = st * 32;
            const float* B = X + ((size_t)b * CD + k0) * NND + n0;
            const int row = t >> 3, cb = (t & 7) * 16;
#pragma unroll
            for (int i = 0; i < 4; i++) {
                int col = cb + i * 4;
                float4 v = *(const float4*)(B + (size_t)row * NND + col);
                ull vh, vl; split4(v, vh, vl);
                *(ull*)&sBh[row * PB + col] = vh;
                *(ull*)&sBl[row * PB + col] = vl;
            }
        }
        __syncthreads();

#pragma unroll
        for (int kk = 0; kk < 32; kk += 16) {
            uint32_t ah[2][4], al[2][4];
#pragma unroll
            for (int i = 0; i < 2; i++) {
                uint32_t off = (uint32_t)(((m0w + i * 16 + (L & 15)) * PA
                                + kk + ((L >> 4) << 3)) * 2);
                LDSM4(ah[i][0], ah[i][1], ah[i][2], ah[i][3], uAh + off);
                LDSM4(al[i][0], al[i][1], al[i][2], al[i][3], uAl + off);
            }
#pragma unroll
            for (int j2 = 0; j2 < 4; j2++) {
                uint32_t h0, h1, h2, h3, l0, l1, l2, l3;
                uint32_t off = (uint32_t)(((kk + (L & 15)) * PB
                                + n0w + j2 * 16 + ((L >> 4) << 3)) * 2);
                LDSM4T(h0, h1, h2, h3, uBh + off);
                LDSM4T(l0, l1, l2, l3, uBl + off);
#pragma unroll
                for (int i = 0; i < 2; i++) {
                    MMA16816(acc[i][2 * j2],     ah[i], h0, h1);
                    MMA16816(acc[i][2 * j2],     ah[i], l0, l1);
                    MMA16816(acc[i][2 * j2],     al[i], h0, h1);
                    MMA16816(acc[i][2 * j2 + 1], ah[i], h2, h3);
                    MMA16816(acc[i][2 * j2 + 1], ah[i], l2, l3);
                    MMA16816(acc[i][2 * j2 + 1], al[i], h2, h3);
                }
            }
        }
        __syncthreads();
    }

    const int r4 = L >> 2, c2 = (L & 3) * 2;
#pragma unroll
    for (int i = 0; i < 2; i++) {
        const int rA = m0w + i * 16 + r4;
        const float b1 = bias[rA], b2 = bias[rA + 8];
#pragma unroll
        for (int j = 0; j < 8; j++) {
            const int col = n0 + n0w + j * 8 + c2;
            *(float2*)(Y + ((size_t)(b * CD + rA)) * NND + col) =
                make_float2(acc[i][j][0] + b1, acc[i][j][1] + b1);
            *(float2*)(Y + ((size_t)(b * CD + rA + 8)) * NND + col) =
                make_float2(acc[i][j][2] + b2, acc[i][j][3] + b2);
        }
    }
}

// ---------------------------------------------------------------------------
// reduce_scale: 4 independent partial sums over ch (MLP >= 4).
// ---------------------------------------------------------------------------
__global__ void reduce_scale()
{
    const int bd = blockIdx.x;
    const int c  = threadIdx.x;
    const int b  = bd >> 7, d = bd & 127;

    __shared__ float red[128];
    const float* sp = g_sumP + (size_t)b * 128 * 2 * CD;
    red[c] = sp[(c * 2 + 0) * CD + d] + sp[(c * 2 + 1) * CD + d];
    __syncthreads();
    for (int off = 64; off > 0; off >>= 1) {
        if (c < off) red[c] += red[c + off];
        __syncthreads();
    }
    const float inv = 1.0f / red[0];

    const float* p = g_Spart + (size_t)(b * NCH) * CD * CD + (size_t)d * CD + c;
    float s0 = 0.f, s1 = 0.f, s2 = 0.f, s3 = 0.f;
#pragma unroll
    for (int ch = 0; ch < NCH; ch += 4) {
        s0 += p[(size_t)(ch + 0) * CD * CD];
        s1 += p[(size_t)(ch + 1) * CD * CD];
        s2 += p[(size_t)(ch + 2) * CD * CD];
        s3 += p[(size_t)(ch + 3) * CD * CD];
    }
    g_S[(size_t)bd * CD + c] = ((s0 + s1) + (s2 + s3)) * inv;
}

// ---------------------------------------------------------------------------
// ctxu_kernel: per (b, h). ctx (smem) then head-h columns of U.
// ---------------------------------------------------------------------------
#define PS 133
__global__ __launch_bounds__(256) void ctxu_kernel(
    const float* __restrict__ w_qkv, const float* __restrict__ w_out)
{
    const int b = blockIdx.x, h = blockIdx.y;
    __shared__ float sS[32 * PS];      // reused as sWo[128][33] in stage 2
    __shared__ float sV[32 * PS];
    __shared__ float sCtx[32 * 33];
    const int t = threadIdx.x;

#pragma unroll
    for (int p = 0; p < 16; p++) {
        int idx = p * 256 + t;
        int row = idx >> 7, c = idx & 127;
        sS[row * PS + c] = g_S[(size_t)(b * CD + h * 32 + row) * CD + c];
        sV[row * PS + c] = w_qkv[(256 + h * 32 + row) * CD + c];
    }
    __syncthreads();

#pragma unroll
    for (int p = 0; p < 4; p++) {
        int idx = p * 256 + t;
        int d_ = idx >> 5, e = idx & 31;
        float a = 0.f;
#pragma unroll 4
        for (int c = 0; c < CD; c++) a += sS[d_ * PS + c] * sV[e * PS + c];
        sCtx[d_ * 33 + e] = a;
    }
    __syncthreads();

    float* sWo = sS;
#pragma unroll
    for (int p = 0; p < 16; p++) {
        int idx = p * 256 + t;
        int o = idx >> 5, e = idx & 31;
        sWo[o * 33 + e] = w_out[o * CD + h * 32 + e];
    }
    __syncthreads();

    const int og = t >> 5, d_ = t & 31;
#pragma unroll
    for (int p = 0; p < 16; p++) {
        int o = p * 8 + og;
        float a = 0.f;
#pragma unroll
        for (int e = 0; e < 32; e++) a += sWo[o * 33 + e] * sCtx[d_ * 33 + e];
        g_U[(size_t)b * CD * CD + o * CD + h * 32 + d_] = a;
    }
}

// ---------------------------------------------------------------------------
// m_kernel: M[b][o][c] = sum_k U[b][o][k] * Wq[k][c]
// grid (8 b, 4 o-tiles, 4 c-tiles) = 128 blocks; 256 threads, 4 outputs each.
// Serial k 0..127 per output — identical order to previous version.
// ---------------------------------------------------------------------------
__global__ __launch_bounds__(256) void m_kernel(const float* __restrict__ w_qkv)
{
    const int b = blockIdx.x, ot = blockIdx.y, ct = blockIdx.z;
    __shared__ float sU[32 * 132];   // rows o0..o0+31, all 128 k
    __shared__ float sQ[128 * 36];   // all 128 k, cols c0..c0+31
    const int t = threadIdx.x;

#pragma unroll
    for (int p = 0; p < 16; p++) {
        int idx = p * 256 + t;
        int row = idx >> 7, k = idx & 127;
        sU[row * 132 + k] = g_U[(size_t)b * CD * CD + (ot * 32 + row) * CD + k];
    }
#pragma unroll
    for (int p = 0; p < 16; p++) {
        int idx = p * 256 + t;
        int k = idx >> 5, cc = idx & 31;
        sQ[k * 36 + cc] = w_qkv[k * CD + ct * 32 + cc];
    }
    __syncthreads();

    const int og = t >> 5, cl = t & 31;
    float a[4] = {0.f, 0.f, 0.f, 0.f};
    for (int k = 0; k < 128; k++) {
        float qv = sQ[k * 36 + cl];
#pragma unroll
        for (int i = 0; i < 4; i++) a[i] += sU[(og * 4 + i) * 132 + k] * qv;
    }
#pragma unroll
    for (int i = 0; i < 4; i++)
        g_M[(size_t)b * CD * CD + (ot * 32 + og * 4 + i) * CD + ct * 32 + cl] = a[i];
}

// ---------------------------------------------------------------------------
// kernel_launch: stateless; unconditional idempotent attribute call + launches.
// ---------------------------------------------------------------------------
extern "C" void kernel_launch(void* const* d_in, const int* in_sizes, int n_in,
                              void* d_out, int out_size)
{
    const float* x     = (const float*)d_in[0];
    const float* w_qkv = (const float*)d_in[1];
    const float* w_out = (const float*)d_in[2];
    const float* b_out = (const float*)d_in[3];
    float* y = (float*)d_out;

    cudaFuncSetAttribute(fused_es, cudaFuncAttributeMaxDynamicSharedMemorySize, SMEM_FUSED);

    fused_es<<<dim3(NCH, BATCH), 256, SMEM_FUSED>>>(w_qkv + 128 * CD, x);
    reduce_scale<<<1024, 128>>>();
    ctxu_kernel<<<dim3(BATCH, 4), 256>>>(w_qkv, w_out);
    m_kernel<<<dim3(BATCH, 4, 4), 256>>>(w_qkv);
    gemm_out<<<dim3(128, BATCH), 256>>>(x, b_out, y);
}